// round 5
// baseline (speedup 1.0000x reference)
#include <cuda_runtime.h>
#include <math.h>
#include <stdint.h>

#define BB 16
#define CC 256
#define HH 96
#define WW 96
#define GG 16
#define CPG (CC/GG)          // 16
#define HWP (HH*WW)          // 9216
#define NTOT (BB*CC*HWP)     // 37748736
#define GROUPN (CPG*HWP)     // 147456
#define NBX 72               // pixel-tile blocks per (b, by)

// Scratch (device globals: no allocations allowed)
__device__ float g_buf0[NTOT];
__device__ float g_buf1[NTOT];
__device__ float g_buf2[NTOT];
__device__ float g_mean[BB*GG];
__device__ float g_rstd[BB*GG];
// Deterministic per-block GN partial sums: [b][by][gsub 8][bx 72]
__device__ float g_ps [BB*2*8*NBX];
__device__ float g_ps2[BB*2*8*NBX];

__device__ __forceinline__ float sigf(float x){ return 1.0f/(1.0f+expf(-x)); }

// ---------------------------------------------------------------------------
// Tensor-core GEMM (3xTF32 split precision, ~fp32 accuracy):
//   Y[b][o][p] = sum_c A[o][c] * X[b][c][p]
// hi/lo split precomputed into smem at tile-load time -> inner loop is pure
// LDS + HMMA. Block 128x128, BK=16, 8 warps (2M x 4N), warp 64x32, m16n8k8.
// EPI=1: sigmoid(v+bias[o]). STATS=1: emit per-block group sums (determ.).
// ---------------------------------------------------------------------------
__device__ __forceinline__ void mma_tf32(float c[4], const uint32_t a[4], const uint32_t b[2]) {
    asm volatile(
        "mma.sync.aligned.m16n8k8.row.col.f32.tf32.tf32.f32 "
        "{%0,%1,%2,%3}, {%4,%5,%6,%7}, {%8,%9}, {%0,%1,%2,%3};\n"
        : "+f"(c[0]), "+f"(c[1]), "+f"(c[2]), "+f"(c[3])
        : "r"(a[0]), "r"(a[1]), "r"(a[2]), "r"(a[3]), "r"(b[0]), "r"(b[1]));
}

__device__ __forceinline__ void split_tf32(float x, float& hi, float& lo) {
    uint32_t xb = __float_as_uint(x) & 0xffffe000u;   // truncate to tf32
    hi = __uint_as_float(xb);
    lo = x - hi;                                      // residual (exact in fp32)
}

template<int EPI, int STATS>
__global__ __launch_bounds__(256, 2) void gemm_tc(
    const float* __restrict__ A, const float* __restrict__ X,
    float* __restrict__ Y, const float* __restrict__ bias,
    float* __restrict__ ps, float* __restrict__ ps2)
{
    const int BK = 16;
    const int LD = 136;                 // row pitch (floats): conflict-free frag loads
    __shared__ __align__(16) float Ah[BK * LD];   // [k][m] hi
    __shared__ __align__(16) float Al[BK * LD];   // [k][m] lo
    __shared__ __align__(16) float Bh[BK * LD];   // [k][n] hi
    __shared__ __align__(16) float Bl[BK * LD];   // [k][n] lo
    __shared__ float sred[32], sred2[32];

    const int b   = blockIdx.z;
    const int om0 = blockIdx.y * 128;
    const int pn0 = blockIdx.x * 128;
    const int tid = threadIdx.x;
    const int lane = tid & 31;
    const int warp = tid >> 5;
    const int wm = (warp >> 2) * 64;    // warp M offset (0 or 64)
    const int wn = (warp & 3) * 32;     // warp N offset
    const int r  = lane >> 2;           // 0..7
    const int q  = lane & 3;            // 0..3

    const float* Xb = X + (size_t)b * CC * HWP;
    float* Yb       = Y + (size_t)b * CC * HWP;

    float acc[4][4][4];
#pragma unroll
    for (int mi = 0; mi < 4; mi++)
#pragma unroll
        for (int ni = 0; ni < 4; ni++)
#pragma unroll
            for (int k = 0; k < 4; k++) acc[mi][ni][k] = 0.f;

    const int a_row = tid >> 1;             // 0..127
    const int a_kc  = (tid & 1) * 8;        // 0 or 8
    const int b_kr  = tid >> 4;             // 0..15
    const int b_pc  = (tid & 15) * 8;       // 0..120

    for (int k0 = 0; k0 < CC; k0 += BK) {
        // A tile: 128 rows x 16 k, split into hi/lo at store
        {
            const float* ap = A + (size_t)(om0 + a_row) * CC + k0 + a_kc;
            float4 v0 = *(const float4*)ap;
            float4 v1 = *(const float4*)(ap + 4);
            float h0,l0,h1,l1,h2,l2,h3,l3;
            split_tf32(v0.x,h0,l0); split_tf32(v0.y,h1,l1);
            split_tf32(v0.z,h2,l2); split_tf32(v0.w,h3,l3);
            Ah[(a_kc+0)*LD + a_row] = h0; Al[(a_kc+0)*LD + a_row] = l0;
            Ah[(a_kc+1)*LD + a_row] = h1; Al[(a_kc+1)*LD + a_row] = l1;
            Ah[(a_kc+2)*LD + a_row] = h2; Al[(a_kc+2)*LD + a_row] = l2;
            Ah[(a_kc+3)*LD + a_row] = h3; Al[(a_kc+3)*LD + a_row] = l3;
            split_tf32(v1.x,h0,l0); split_tf32(v1.y,h1,l1);
            split_tf32(v1.z,h2,l2); split_tf32(v1.w,h3,l3);
            Ah[(a_kc+4)*LD + a_row] = h0; Al[(a_kc+4)*LD + a_row] = l0;
            Ah[(a_kc+5)*LD + a_row] = h1; Al[(a_kc+5)*LD + a_row] = l1;
            Ah[(a_kc+6)*LD + a_row] = h2; Al[(a_kc+6)*LD + a_row] = l2;
            Ah[(a_kc+7)*LD + a_row] = h3; Al[(a_kc+7)*LD + a_row] = l3;
        }
        // B tile: 16 k-rows x 128 pixels, split into hi/lo at store
        {
            const float* bp = Xb + (size_t)(k0 + b_kr) * HWP + pn0 + b_pc;
            float4 v0 = *(const float4*)bp;
            float4 v1 = *(const float4*)(bp + 4);
            float4 hh, ll;
            split_tf32(v0.x,hh.x,ll.x); split_tf32(v0.y,hh.y,ll.y);
            split_tf32(v0.z,hh.z,ll.z); split_tf32(v0.w,hh.w,ll.w);
            *(float4*)&Bh[b_kr*LD + b_pc] = hh;
            *(float4*)&Bl[b_kr*LD + b_pc] = ll;
            split_tf32(v1.x,hh.x,ll.x); split_tf32(v1.y,hh.y,ll.y);
            split_tf32(v1.z,hh.z,ll.z); split_tf32(v1.w,hh.w,ll.w);
            *(float4*)&Bh[b_kr*LD + b_pc + 4] = hh;
            *(float4*)&Bl[b_kr*LD + b_pc + 4] = ll;
        }
        __syncthreads();

#pragma unroll
        for (int ks = 0; ks < BK; ks += 8) {
            uint32_t ah[4][4], al[4][4];
#pragma unroll
            for (int mi = 0; mi < 4; mi++) {
                int m0 = wm + mi*16 + r;
                ah[mi][0] = __float_as_uint(Ah[(ks+q  )*LD + m0    ]);
                ah[mi][1] = __float_as_uint(Ah[(ks+q  )*LD + m0 + 8]);
                ah[mi][2] = __float_as_uint(Ah[(ks+q+4)*LD + m0    ]);
                ah[mi][3] = __float_as_uint(Ah[(ks+q+4)*LD + m0 + 8]);
                al[mi][0] = __float_as_uint(Al[(ks+q  )*LD + m0    ]);
                al[mi][1] = __float_as_uint(Al[(ks+q  )*LD + m0 + 8]);
                al[mi][2] = __float_as_uint(Al[(ks+q+4)*LD + m0    ]);
                al[mi][3] = __float_as_uint(Al[(ks+q+4)*LD + m0 + 8]);
            }
#pragma unroll
            for (int ni = 0; ni < 4; ni++) {
                int n0 = wn + ni*8 + r;
                uint32_t bh[2], bl[2];
                bh[0] = __float_as_uint(Bh[(ks+q  )*LD + n0]);
                bh[1] = __float_as_uint(Bh[(ks+q+4)*LD + n0]);
                bl[0] = __float_as_uint(Bl[(ks+q  )*LD + n0]);
                bl[1] = __float_as_uint(Bl[(ks+q+4)*LD + n0]);
#pragma unroll
                for (int mi = 0; mi < 4; mi++) {
                    mma_tf32(acc[mi][ni], ah[mi], bh);   // hi*hi
                    mma_tf32(acc[mi][ni], al[mi], bh);   // lo*hi
                    mma_tf32(acc[mi][ni], ah[mi], bl);   // hi*lo
                }
            }
        }
        __syncthreads();
    }

    // Epilogue. c0:(r, 2q) c1:(r, 2q+1) c2:(r+8, 2q) c3:(r+8, 2q+1)
#pragma unroll
    for (int mi = 0; mi < 4; mi++) {
        int o0 = om0 + wm + mi*16 + r;
        float bo0 = 0.f, bo1 = 0.f;
        if (EPI == 1) { bo0 = bias[o0]; bo1 = bias[o0 + 8]; }
#pragma unroll
        for (int ni = 0; ni < 4; ni++) {
            int p = pn0 + wn + ni*8 + 2*q;
            float2 v0, v1;
            v0.x = acc[mi][ni][0]; v0.y = acc[mi][ni][1];
            v1.x = acc[mi][ni][2]; v1.y = acc[mi][ni][3];
            if (EPI == 1) {
                v0.x = sigf(v0.x + bo0); v0.y = sigf(v0.y + bo0);
                v1.x = sigf(v1.x + bo1); v1.y = sigf(v1.y + bo1);
            }
            *(float2*)&Yb[(size_t)o0 * HWP + p]       = v0;
            *(float2*)&Yb[(size_t)(o0+8) * HWP + p]   = v1;
        }
    }

    if (STATS) {
        // Each mi-tile of rows lies entirely in one channel group (16 rows).
#pragma unroll
        for (int mi = 0; mi < 4; mi++) {
            float s = 0.f, s2 = 0.f;
#pragma unroll
            for (int ni = 0; ni < 4; ni++)
#pragma unroll
                for (int k = 0; k < 4; k++) {
                    float v = acc[mi][ni][k];
                    s += v; s2 += v*v;
                }
#pragma unroll
            for (int m = 16; m > 0; m >>= 1) {
                s  += __shfl_xor_sync(0xffffffffu, s,  m);
                s2 += __shfl_xor_sync(0xffffffffu, s2, m);
            }
            if (lane == 0) { sred[warp*4 + mi] = s; sred2[warp*4 + mi] = s2; }
        }
        __syncthreads();
        if (tid < 8) {
            int wmIdx = tid >> 2, mi = tid & 3;
            float s = 0.f, s2 = 0.f;
#pragma unroll
            for (int nIdx = 0; nIdx < 4; nIdx++) {
                int w = wmIdx*4 + nIdx;
                s += sred[w*4 + mi]; s2 += sred2[w*4 + mi];
            }
            int gsub = wmIdx*4 + mi;   // = (wm + mi*16)/16
            int idx = ((b*2 + blockIdx.y)*8 + gsub)*NBX + blockIdx.x;
            ps[idx] = s; ps2[idx] = s2;
        }
    }
}

// ---------------------------------------------------------------------------
// Finalize GN stats from per-block partials. 256 threads, one per (b, group).
// ---------------------------------------------------------------------------
__global__ void finalize_stats(const float* __restrict__ ps, const float* __restrict__ ps2)
{
    int bg = threadIdx.x;          // b*16 + group ; matches partial layout
    int base = bg * NBX;
    float s = 0.f, s2 = 0.f;
    for (int i = 0; i < NBX; i++) { s += ps[base+i]; s2 += ps2[base+i]; }
    float mean = s / (float)GROUPN;
    float var  = s2 / (float)GROUPN - mean*mean;
    g_mean[bg] = mean;
    g_rstd[bg] = rsqrtf(var + 1e-5f);
}

// ---------------------------------------------------------------------------
// Apply group norm + SiLU (vectorized float4)
// ---------------------------------------------------------------------------
__global__ __launch_bounds__(256) void gn_silu_kernel(
    const float* __restrict__ in, float* __restrict__ out,
    const float* __restrict__ gw, const float* __restrict__ gb)
{
    int i4 = blockIdx.x * 256 + threadIdx.x;
    if (i4 >= NTOT/4) return;
    size_t idx = (size_t)i4 * 4;
    int c = (int)((idx / HWP) % CC);
    int b = (int)(idx / ((size_t)CC * HWP));
    int bg = b * GG + c / CPG;
    float m = g_mean[bg], rs = g_rstd[bg];
    float sw = gw[c] * rs;
    float sb = gb[c] - m * sw;
    float4 v = *(const float4*)&in[idx];
    float y;
    y = fmaf(v.x, sw, sb); v.x = y * sigf(y);
    y = fmaf(v.y, sw, sb); v.y = y * sigf(y);
    y = fmaf(v.z, sw, sb); v.z = y * sigf(y);
    y = fmaf(v.w, sw, sb); v.w = y * sigf(y);
    *(float4*)&out[idx] = v;
}

// ---------------------------------------------------------------------------
// W-direction scans (lr forward + rl backward). One thread per (b,c,h) row.
// out = lr + rl
// ---------------------------------------------------------------------------
__global__ __launch_bounds__(256) void scanW_kernel(
    const float* __restrict__ xp, float* __restrict__ out,
    const float* __restrict__ a_p, const float* __restrict__ b_p,
    const float* __restrict__ c_p, const float* __restrict__ d_p)
{
    int r = blockIdx.x * 256 + threadIdx.x;
    if (r >= BB*CC*HH) return;
    int c = (r / HH) % CC;
    float a0 = sigf(a_p[c]),      b0 = b_p[c],      c0 = c_p[c],      d0 = d_p[c];
    float a1 = sigf(a_p[CC + c]), b1 = b_p[CC + c], c1 = c_p[CC + c], d1 = d_p[CC + c];
    size_t base = (size_t)r * WW;

    float h = 0.f;
    for (int i0 = 0; i0 < WW; i0 += 4) {
        float4 x = *(const float4*)&xp[base + i0];
        float4 y;
        h = fmaf(a0, h, b0 * x.x); y.x = fmaf(c0, h, d0 * x.x);
        h = fmaf(a0, h, b0 * x.y); y.y = fmaf(c0, h, d0 * x.y);
        h = fmaf(a0, h, b0 * x.z); y.z = fmaf(c0, h, d0 * x.z);
        h = fmaf(a0, h, b0 * x.w); y.w = fmaf(c0, h, d0 * x.w);
        *(float4*)&out[base + i0] = y;
    }
    h = 0.f;
    for (int i0 = WW - 4; i0 >= 0; i0 -= 4) {
        float4 x = *(const float4*)&xp[base + i0];
        float4 o = *(float4*)&out[base + i0];
        h = fmaf(a1, h, b1 * x.w); o.w += fmaf(c1, h, d1 * x.w);
        h = fmaf(a1, h, b1 * x.z); o.z += fmaf(c1, h, d1 * x.z);
        h = fmaf(a1, h, b1 * x.y); o.y += fmaf(c1, h, d1 * x.y);
        h = fmaf(a1, h, b1 * x.x); o.x += fmaf(c1, h, d1 * x.x);
        *(float4*)&out[base + i0] = o;
    }
}

// ---------------------------------------------------------------------------
// H-direction scans (tb forward + bt backward) + final combine with gate.
// ---------------------------------------------------------------------------
__global__ __launch_bounds__(256) void scanH_kernel(
    const float* __restrict__ xp, const float* __restrict__ gate,
    float* __restrict__ acc,
    const float* __restrict__ a_p, const float* __restrict__ b_p,
    const float* __restrict__ c_p, const float* __restrict__ d_p)
{
    int t = blockIdx.x * 256 + threadIdx.x;
    if (t >= BB*CC*(WW/4)) return;
    int wq = t % (WW/4);
    int bc = t / (WW/4);
    int c  = bc % CC;
    float a2 = sigf(a_p[2*CC + c]), b2 = b_p[2*CC + c], c2 = c_p[2*CC + c], d2 = d_p[2*CC + c];
    float a3 = sigf(a_p[3*CC + c]), b3 = b_p[3*CC + c], c3 = c_p[3*CC + c], d3 = d_p[3*CC + c];
    size_t base = (size_t)bc * HWP + wq * 4;

    float4 h = make_float4(0.f, 0.f, 0.f, 0.f);
    for (int j = 0; j < HH; j++) {
        size_t off = base + (size_t)j * WW;
        float4 x = *(const float4*)&xp[off];
        float4 o = *(float4*)&acc[off];
        h.x = fmaf(a2, h.x, b2 * x.x); o.x += fmaf(c2, h.x, d2 * x.x);
        h.y = fmaf(a2, h.y, b2 * x.y); o.y += fmaf(c2, h.y, d2 * x.y);
        h.z = fmaf(a2, h.z, b2 * x.z); o.z += fmaf(c2, h.z, d2 * x.z);
        h.w = fmaf(a2, h.w, b2 * x.w); o.w += fmaf(c2, h.w, d2 * x.w);
        *(float4*)&acc[off] = o;
    }
    h = make_float4(0.f, 0.f, 0.f, 0.f);
    for (int j = HH - 1; j >= 0; j--) {
        size_t off = base + (size_t)j * WW;
        float4 x = *(const float4*)&xp[off];
        float4 o = *(float4*)&acc[off];
        float4 g = *(const float4*)&gate[off];
        h.x = fmaf(a3, h.x, b3 * x.x); o.x = 0.25f * (o.x + fmaf(c3, h.x, d3 * x.x)) * g.x;
        h.y = fmaf(a3, h.y, b3 * x.y); o.y = 0.25f * (o.y + fmaf(c3, h.y, d3 * x.y)) * g.y;
        h.z = fmaf(a3, h.z, b3 * x.z); o.z = 0.25f * (o.z + fmaf(c3, h.z, d3 * x.z)) * g.z;
        h.w = fmaf(a3, h.w, b3 * x.w); o.w = 0.25f * (o.w + fmaf(c3, h.w, d3 * x.w)) * g.w;
        *(float4*)&acc[off] = o;
    }
}

// ---------------------------------------------------------------------------
// Depthwise 3x3 conv, SAME zero padding. One thread per output pixel.
// ---------------------------------------------------------------------------
__global__ __launch_bounds__(256) void dw_kernel(
    const float* __restrict__ in, const float* __restrict__ wt,
    float* __restrict__ out)
{
    int idx = blockIdx.x * 256 + threadIdx.x;
    if (idx >= NTOT) return;
    int w = idx % WW;
    int h = (idx / WW) % HH;
    int c = (idx / HWP) % CC;
    const float* pk = wt + c * 9;
    float k0 = pk[0], k1 = pk[1], k2 = pk[2];
    float k3 = pk[3], k4 = pk[4], k5 = pk[5];
    float k6 = pk[6], k7 = pk[7], k8 = pk[8];
    const float* pl = in + (size_t)(idx / HWP) * HWP;
    float s = 0.f;
    if (h > 0) {
        const float* rr = pl + (size_t)(h-1) * WW;
        if (w > 0)    s = fmaf(rr[w-1], k0, s);
                      s = fmaf(rr[w],   k1, s);
        if (w < WW-1) s = fmaf(rr[w+1], k2, s);
    }
    {
        const float* rr = pl + (size_t)h * WW;
        if (w > 0)    s = fmaf(rr[w-1], k3, s);
                      s = fmaf(rr[w],   k4, s);
        if (w < WW-1) s = fmaf(rr[w+1], k5, s);
    }
    if (h < HH-1) {
        const float* rr = pl + (size_t)(h+1) * WW;
        if (w > 0)    s = fmaf(rr[w-1], k6, s);
                      s = fmaf(rr[w],   k7, s);
        if (w < WW-1) s = fmaf(rr[w+1], k8, s);
    }
    out[idx] = s;
}

// ---------------------------------------------------------------------------
extern "C" void kernel_launch(void* const* d_in, const int* in_sizes, int n_in,
                              void* d_out, int out_size)
{
    const float* x      = (const float*)d_in[0];
    const float* in_w   = (const float*)d_in[1];
    const float* gn1_w  = (const float*)d_in[2];
    const float* gn1_b  = (const float*)d_in[3];
    const float* a_p    = (const float*)d_in[4];
    const float* b_p    = (const float*)d_in[5];
    const float* c_p    = (const float*)d_in[6];
    const float* d_p    = (const float*)d_in[7];
    const float* gate_w = (const float*)d_in[8];
    const float* gate_b = (const float*)d_in[9];
    const float* dw_w   = (const float*)d_in[10];
    const float* pw_w   = (const float*)d_in[11];
    const float* gn2_w  = (const float*)d_in[12];
    const float* gn2_b  = (const float*)d_in[13];
    float* out = (float*)d_out;

    float *buf0, *buf1, *buf2, *ps, *ps2;
    cudaGetSymbolAddress((void**)&buf0, g_buf0);
    cudaGetSymbolAddress((void**)&buf1, g_buf1);
    cudaGetSymbolAddress((void**)&buf2, g_buf2);
    cudaGetSymbolAddress((void**)&ps,  g_ps);
    cudaGetSymbolAddress((void**)&ps2, g_ps2);

    dim3 ggrid(HWP/128, CC/128, BB);   // (72, 2, 16)
    int elem4_blocks = (NTOT/4 + 255) / 256;       // 36864
    int scanW_blocks = (BB*CC*HH + 255) / 256;     // 1536
    int scanH_blocks = (BB*CC*(WW/4) + 255) / 256; // 384
    int dw_blocks    = (NTOT + 255) / 256;         // 147456

    // 1. xp_raw = in_w @ x   (+ fused GN1 partial stats)
    gemm_tc<0,1><<<ggrid, 256>>>(in_w, x, buf0, nullptr, ps, ps2);
    // 2. finalize gn1 stats
    finalize_stats<<<1, 256>>>(ps, ps2);
    // 3. xp = silu(gn1(xp_raw))
    gn_silu_kernel<<<elem4_blocks, 256>>>(buf0, buf1, gn1_w, gn1_b);
    // 4. gate = sigmoid(gate_w @ xp + gate_b)
    gemm_tc<1,0><<<ggrid, 256>>>(gate_w, buf1, buf0, gate_b, nullptr, nullptr);
    // 5. buf2 = lr + rl
    scanW_kernel<<<scanW_blocks, 256>>>(buf1, buf2, a_p, b_p, c_p, d_p);
    // 6. buf2 = 0.25*(lr+rl+tb+bt)*gate
    scanH_kernel<<<scanH_blocks, 256>>>(buf1, buf0, buf2, a_p, b_p, c_p, d_p);
    // 7. depthwise 3x3
    dw_kernel<<<dw_blocks, 256>>>(buf2, dw_w, buf1);
    // 8. out_raw = pw_w @ dw   (+ fused GN2 partial stats)
    gemm_tc<0,1><<<ggrid, 256>>>(pw_w, buf1, buf0, nullptr, ps, ps2);
    // 9. finalize gn2 stats
    finalize_stats<<<1, 256>>>(ps, ps2);
    // 10. out = silu(gn2(out_raw))
    gn_silu_kernel<<<elem4_blocks, 256>>>(buf0, out, gn2_w, gn2_b);
}

// round 9
// speedup vs baseline: 1.1190x; 1.1190x over previous
#include <cuda_runtime.h>
#include <math.h>
#include <stdint.h>

#define BB 16
#define CC 256
#define HH 96
#define WW 96
#define GG 16
#define CPG (CC/GG)          // 16
#define HWP (HH*WW)          // 9216
#define NTOT (BB*CC*HWP)     // 37748736
#define GROUPN (CPG*HWP)     // 147456
#define NBX 72               // pixel-tile blocks per (b, by)

// Scratch (device globals: no allocations allowed)
__device__ float g_buf0[NTOT];
__device__ float g_buf1[NTOT];
__device__ float g_buf2[NTOT];
__device__ float g_mean[BB*GG];
__device__ float g_rstd[BB*GG];
// Deterministic per-block GN partial sums: [b][by][gsub 8][bx 72]
__device__ float g_ps [BB*2*8*NBX];
__device__ float g_ps2[BB*2*8*NBX];

__device__ __forceinline__ float sigf(float x){ return 1.0f/(1.0f+expf(-x)); }

__device__ __forceinline__ uint32_t smem_u32(const void* p) {
    uint32_t a;
    asm("{ .reg .u64 t; cvta.to.shared.u64 t, %1; cvt.u32.u64 %0, t; }" : "=r"(a) : "l"(p));
    return a;
}
__device__ __forceinline__ void cp16(uint32_t dst, const float* src) {
    asm volatile("cp.async.cg.shared.global [%0], [%1], 16;" :: "r"(dst), "l"(src));
}

// ---------------------------------------------------------------------------
// Tensor-core GEMM (3xTF32 split precision, ~fp32 accuracy):
//   Y[b][o][p] = sum_c A[o][c] * X[b][c][p]
// cp.async double-buffered. Block 128x128, BK=16, 8 warps (2M x 4N),
// warp 64x32, m16n8k8. hi/lo split in registers at fragment load (R2-proven).
// A smem layout [m][20] (conflict-free, cp.async w/o transpose); B [k][136].
// EPI=1: sigmoid(v+bias[o]). STATS=1: per-block deterministic GN partials.
// ---------------------------------------------------------------------------
__device__ __forceinline__ void mma_tf32(float c[4], const uint32_t a[4], const uint32_t b[2]) {
    asm volatile(
        "mma.sync.aligned.m16n8k8.row.col.f32.tf32.tf32.f32 "
        "{%0,%1,%2,%3}, {%4,%5,%6,%7}, {%8,%9}, {%0,%1,%2,%3};\n"
        : "+f"(c[0]), "+f"(c[1]), "+f"(c[2]), "+f"(c[3])
        : "r"(a[0]), "r"(a[1]), "r"(a[2]), "r"(a[3]), "r"(b[0]), "r"(b[1]));
}
__device__ __forceinline__ void split_tf32(float x, uint32_t& hi, uint32_t& lo) {
    uint32_t xb = __float_as_uint(x) & 0xffffe000u;   // truncate to tf32
    hi = xb;
    lo = __float_as_uint(x - __uint_as_float(xb));    // residual (exact in fp32)
}

#define LDA 20
#define LDB 136
#define A_BUF (128*LDA)      // floats
#define B_BUF (16*LDB)

template<int EPI, int STATS>
__global__ __launch_bounds__(256, 2) void gemm_tc(
    const float* __restrict__ A, const float* __restrict__ X,
    float* __restrict__ Y, const float* __restrict__ bias,
    float* __restrict__ ps, float* __restrict__ ps2)
{
    __shared__ __align__(16) float AsT[2*A_BUF];   // [buf][m][k] pitch 20
    __shared__ __align__(16) float Bs [2*B_BUF];   // [buf][k][n] pitch 136
    __shared__ float sred[32], sred2[32];

    const int b   = blockIdx.z;
    const int om0 = blockIdx.y * 128;
    const int pn0 = blockIdx.x * 128;
    const int tid = threadIdx.x;
    const int lane = tid & 31;
    const int warp = tid >> 5;
    const int wm = (warp >> 2) * 64;
    const int wn = (warp & 3) * 32;
    const int r  = lane >> 2;
    const int q  = lane & 3;

    const float* Xb = X + (size_t)b * CC * HWP;
    float* Yb       = Y + (size_t)b * CC * HWP;

    const uint32_t a_smem = smem_u32(AsT);
    const uint32_t b_smem = smem_u32(Bs);

    // cp.async chunk mapping (2 chunks each for A and B per thread per tile)
    const int am0 = (tid       ) >> 2, akq0 = ((tid       ) & 3) * 4;
    const int am1 = (tid + 256 ) >> 2, akq1 = ((tid + 256 ) & 3) * 4;
    const int bk0 = (tid       ) >> 5, bnq0 = ((tid       ) & 31) * 4;
    const int bk1 = (tid + 256 ) >> 5, bnq1 = ((tid + 256 ) & 31) * 4;

#define ISSUE_TILE(S, BUF) do { \
        int k0 = (S) * 16; \
        cp16(a_smem + (uint32_t)((BUF)*A_BUF + am0*LDA + akq0)*4, A + (size_t)(om0+am0)*CC + k0 + akq0); \
        cp16(a_smem + (uint32_t)((BUF)*A_BUF + am1*LDA + akq1)*4, A + (size_t)(om0+am1)*CC + k0 + akq1); \
        cp16(b_smem + (uint32_t)((BUF)*B_BUF + bk0*LDB + bnq0)*4, Xb + (size_t)(k0+bk0)*HWP + pn0 + bnq0); \
        cp16(b_smem + (uint32_t)((BUF)*B_BUF + bk1*LDB + bnq1)*4, Xb + (size_t)(k0+bk1)*HWP + pn0 + bnq1); \
        asm volatile("cp.async.commit_group;"); \
    } while (0)

    float acc[4][4][4];
#pragma unroll
    for (int mi = 0; mi < 4; mi++)
#pragma unroll
        for (int ni = 0; ni < 4; ni++)
#pragma unroll
            for (int k = 0; k < 4; k++) acc[mi][ni][k] = 0.f;

    ISSUE_TILE(0, 0);

    for (int s = 0; s < 16; s++) {
        const int buf = s & 1;
        if (s < 15) {
            ISSUE_TILE(s + 1, buf ^ 1);
            asm volatile("cp.async.wait_group 1;");
        } else {
            asm volatile("cp.async.wait_group 0;");
        }
        __syncthreads();

        const float* Ab = AsT + buf * A_BUF;
        const float* Bb = Bs  + buf * B_BUF;

#pragma unroll
        for (int ks = 0; ks < 16; ks += 8) {
            uint32_t ah[4][4], al[4][4];
#pragma unroll
            for (int mi = 0; mi < 4; mi++) {
                int m0 = wm + mi*16 + r;
                split_tf32(Ab[(m0    )*LDA + ks+q  ], ah[mi][0], al[mi][0]);
                split_tf32(Ab[(m0 + 8)*LDA + ks+q  ], ah[mi][1], al[mi][1]);
                split_tf32(Ab[(m0    )*LDA + ks+q+4], ah[mi][2], al[mi][2]);
                split_tf32(Ab[(m0 + 8)*LDA + ks+q+4], ah[mi][3], al[mi][3]);
            }
#pragma unroll
            for (int ni = 0; ni < 4; ni++) {
                int n0 = wn + ni*8 + r;
                uint32_t bh[2], bl[2];
                split_tf32(Bb[(ks+q  )*LDB + n0], bh[0], bl[0]);
                split_tf32(Bb[(ks+q+4)*LDB + n0], bh[1], bl[1]);
#pragma unroll
                for (int mi = 0; mi < 4; mi++) {
                    mma_tf32(acc[mi][ni], ah[mi], bh);   // hi*hi
                    mma_tf32(acc[mi][ni], al[mi], bh);   // lo*hi
                    mma_tf32(acc[mi][ni], ah[mi], bl);   // hi*lo
                }
            }
        }
        __syncthreads();
    }

    // Epilogue. c0:(r, 2q) c1:(r, 2q+1) c2:(r+8, 2q) c3:(r+8, 2q+1)
#pragma unroll
    for (int mi = 0; mi < 4; mi++) {
        int o0 = om0 + wm + mi*16 + r;
        float bo0 = 0.f, bo1 = 0.f;
        if (EPI == 1) { bo0 = bias[o0]; bo1 = bias[o0 + 8]; }
#pragma unroll
        for (int ni = 0; ni < 4; ni++) {
            int p = pn0 + wn + ni*8 + 2*q;
            float2 v0, v1;
            v0.x = acc[mi][ni][0]; v0.y = acc[mi][ni][1];
            v1.x = acc[mi][ni][2]; v1.y = acc[mi][ni][3];
            if (EPI == 1) {
                v0.x = sigf(v0.x + bo0); v0.y = sigf(v0.y + bo0);
                v1.x = sigf(v1.x + bo1); v1.y = sigf(v1.y + bo1);
            }
            *(float2*)&Yb[(size_t)o0 * HWP + p]       = v0;
            *(float2*)&Yb[(size_t)(o0+8) * HWP + p]   = v1;
        }
    }

    if (STATS) {
        // Each mi-tile of 16 rows lies entirely in one channel group.
#pragma unroll
        for (int mi = 0; mi < 4; mi++) {
            float s = 0.f, s2 = 0.f;
#pragma unroll
            for (int ni = 0; ni < 4; ni++)
#pragma unroll
                for (int k = 0; k < 4; k++) {
                    float v = acc[mi][ni][k];
                    s += v; s2 += v*v;
                }
#pragma unroll
            for (int m = 16; m > 0; m >>= 1) {
                s  += __shfl_xor_sync(0xffffffffu, s,  m);
                s2 += __shfl_xor_sync(0xffffffffu, s2, m);
            }
            if (lane == 0) { sred[warp*4 + mi] = s; sred2[warp*4 + mi] = s2; }
        }
        __syncthreads();
        if (tid < 8) {
            int wmIdx = tid >> 2, mi = tid & 3;
            float s = 0.f, s2 = 0.f;
#pragma unroll
            for (int nIdx = 0; nIdx < 4; nIdx++) {
                int w = wmIdx*4 + nIdx;
                s += sred[w*4 + mi]; s2 += sred2[w*4 + mi];
            }
            int gsub = wmIdx*4 + mi;   // = (wm + mi*16)/16
            int idx = ((b*2 + blockIdx.y)*8 + gsub)*NBX + blockIdx.x;
            ps[idx] = s; ps2[idx] = s2;
        }
    }
#undef ISSUE_TILE
}

// ---------------------------------------------------------------------------
// Finalize GN stats from per-block partials. 256 threads, one per (b, group).
// ---------------------------------------------------------------------------
__global__ void finalize_stats(const float* __restrict__ ps, const float* __restrict__ ps2)
{
    int bg = threadIdx.x;          // b*16 + group ; matches partial layout
    int base = bg * NBX;
    float s = 0.f, s2 = 0.f;
    for (int i = 0; i < NBX; i++) { s += ps[base+i]; s2 += ps2[base+i]; }
    float mean = s / (float)GROUPN;
    float var  = s2 / (float)GROUPN - mean*mean;
    g_mean[bg] = mean;
    g_rstd[bg] = rsqrtf(var + 1e-5f);
}

// ---------------------------------------------------------------------------
// Apply group norm + SiLU (vectorized float4)
// ---------------------------------------------------------------------------
__global__ __launch_bounds__(256) void gn_silu_kernel(
    const float* __restrict__ in, float* __restrict__ out,
    const float* __restrict__ gw, const float* __restrict__ gb)
{
    int i4 = blockIdx.x * 256 + threadIdx.x;
    if (i4 >= NTOT/4) return;
    size_t idx = (size_t)i4 * 4;
    int c = (int)((idx / HWP) % CC);
    int b = (int)(idx / ((size_t)CC * HWP));
    int bg = b * GG + c / CPG;
    float m = g_mean[bg], rs = g_rstd[bg];
    float sw = gw[c] * rs;
    float sb = gb[c] - m * sw;
    float4 v = *(const float4*)&in[idx];
    float y;
    y = fmaf(v.x, sw, sb); v.x = y * sigf(y);
    y = fmaf(v.y, sw, sb); v.y = y * sigf(y);
    y = fmaf(v.z, sw, sb); v.z = y * sigf(y);
    y = fmaf(v.w, sw, sb); v.w = y * sigf(y);
    *(float4*)&out[idx] = v;
}

// ---------------------------------------------------------------------------
// W-direction scans (lr forward + rl backward). One thread per (b,c,h) row.
// ---------------------------------------------------------------------------
__global__ __launch_bounds__(256) void scanW_kernel(
    const float* __restrict__ xp, float* __restrict__ out,
    const float* __restrict__ a_p, const float* __restrict__ b_p,
    const float* __restrict__ c_p, const float* __restrict__ d_p)
{
    int r = blockIdx.x * 256 + threadIdx.x;
    if (r >= BB*CC*HH) return;
    int c = (r / HH) % CC;
    float a0 = sigf(a_p[c]),      b0 = b_p[c],      c0 = c_p[c],      d0 = d_p[c];
    float a1 = sigf(a_p[CC + c]), b1 = b_p[CC + c], c1 = c_p[CC + c], d1 = d_p[CC + c];
    size_t base = (size_t)r * WW;

    float h = 0.f;
    for (int i0 = 0; i0 < WW; i0 += 4) {
        float4 x = *(const float4*)&xp[base + i0];
        float4 y;
        h = fmaf(a0, h, b0 * x.x); y.x = fmaf(c0, h, d0 * x.x);
        h = fmaf(a0, h, b0 * x.y); y.y = fmaf(c0, h, d0 * x.y);
        h = fmaf(a0, h, b0 * x.z); y.z = fmaf(c0, h, d0 * x.z);
        h = fmaf(a0, h, b0 * x.w); y.w = fmaf(c0, h, d0 * x.w);
        *(float4*)&out[base + i0] = y;
    }
    h = 0.f;
    for (int i0 = WW - 4; i0 >= 0; i0 -= 4) {
        float4 x = *(const float4*)&xp[base + i0];
        float4 o = *(float4*)&out[base + i0];
        h = fmaf(a1, h, b1 * x.w); o.w += fmaf(c1, h, d1 * x.w);
        h = fmaf(a1, h, b1 * x.z); o.z += fmaf(c1, h, d1 * x.z);
        h = fmaf(a1, h, b1 * x.y); o.y += fmaf(c1, h, d1 * x.y);
        h = fmaf(a1, h, b1 * x.x); o.x += fmaf(c1, h, d1 * x.x);
        *(float4*)&out[base + i0] = o;
    }
}

// ---------------------------------------------------------------------------
// H-direction scans (tb forward + bt backward) + final combine with gate.
// ---------------------------------------------------------------------------
__global__ __launch_bounds__(256) void scanH_kernel(
    const float* __restrict__ xp, const float* __restrict__ gate,
    float* __restrict__ acc,
    const float* __restrict__ a_p, const float* __restrict__ b_p,
    const float* __restrict__ c_p, const float* __restrict__ d_p)
{
    int t = blockIdx.x * 256 + threadIdx.x;
    if (t >= BB*CC*(WW/4)) return;
    int wq = t % (WW/4);
    int bc = t / (WW/4);
    int c  = bc % CC;
    float a2 = sigf(a_p[2*CC + c]), b2 = b_p[2*CC + c], c2 = c_p[2*CC + c], d2 = d_p[2*CC + c];
    float a3 = sigf(a_p[3*CC + c]), b3 = b_p[3*CC + c], c3 = c_p[3*CC + c], d3 = d_p[3*CC + c];
    size_t base = (size_t)bc * HWP + wq * 4;

    float4 h = make_float4(0.f, 0.f, 0.f, 0.f);
    for (int j = 0; j < HH; j++) {
        size_t off = base + (size_t)j * WW;
        float4 x = *(const float4*)&xp[off];
        float4 o = *(float4*)&acc[off];
        h.x = fmaf(a2, h.x, b2 * x.x); o.x += fmaf(c2, h.x, d2 * x.x);
        h.y = fmaf(a2, h.y, b2 * x.y); o.y += fmaf(c2, h.y, d2 * x.y);
        h.z = fmaf(a2, h.z, b2 * x.z); o.z += fmaf(c2, h.z, d2 * x.z);
        h.w = fmaf(a2, h.w, b2 * x.w); o.w += fmaf(c2, h.w, d2 * x.w);
        *(float4*)&acc[off] = o;
    }
    h = make_float4(0.f, 0.f, 0.f, 0.f);
    for (int j = HH - 1; j >= 0; j--) {
        size_t off = base + (size_t)j * WW;
        float4 x = *(const float4*)&xp[off];
        float4 o = *(float4*)&acc[off];
        float4 g = *(const float4*)&gate[off];
        h.x = fmaf(a3, h.x, b3 * x.x); o.x = 0.25f * (o.x + fmaf(c3, h.x, d3 * x.x)) * g.x;
        h.y = fmaf(a3, h.y, b3 * x.y); o.y = 0.25f * (o.y + fmaf(c3, h.y, d3 * x.y)) * g.y;
        h.z = fmaf(a3, h.z, b3 * x.z); o.z = 0.25f * (o.z + fmaf(c3, h.z, d3 * x.z)) * g.z;
        h.w = fmaf(a3, h.w, b3 * x.w); o.w = 0.25f * (o.w + fmaf(c3, h.w, d3 * x.w)) * g.w;
        *(float4*)&acc[off] = o;
    }
}

// ---------------------------------------------------------------------------
// Depthwise 3x3 conv, SAME zero padding. One thread per output pixel.
// ---------------------------------------------------------------------------
__global__ __launch_bounds__(256) void dw_kernel(
    const float* __restrict__ in, const float* __restrict__ wt,
    float* __restrict__ out)
{
    int idx = blockIdx.x * 256 + threadIdx.x;
    if (idx >= NTOT) return;
    int w = idx % WW;
    int h = (idx / WW) % HH;
    int c = (idx / HWP) % CC;
    const float* pk = wt + c * 9;
    float k0 = pk[0], k1 = pk[1], k2 = pk[2];
    float k3 = pk[3], k4 = pk[4], k5 = pk[5];
    float k6 = pk[6], k7 = pk[7], k8 = pk[8];
    const float* pl = in + (size_t)(idx / HWP) * HWP;
    float s = 0.f;
    if (h > 0) {
        const float* rr = pl + (size_t)(h-1) * WW;
        if (w > 0)    s = fmaf(rr[w-1], k0, s);
                      s = fmaf(rr[w],   k1, s);
        if (w < WW-1) s = fmaf(rr[w+1], k2, s);
    }
    {
        const float* rr = pl + (size_t)h * WW;
        if (w > 0)    s = fmaf(rr[w-1], k3, s);
                      s = fmaf(rr[w],   k4, s);
        if (w < WW-1) s = fmaf(rr[w+1], k5, s);
    }
    if (h < HH-1) {
        const float* rr = pl + (size_t)(h+1) * WW;
        if (w > 0)    s = fmaf(rr[w-1], k6, s);
                      s = fmaf(rr[w],   k7, s);
        if (w < WW-1) s = fmaf(rr[w+1], k8, s);
    }
    out[idx] = s;
}

// ---------------------------------------------------------------------------
extern "C" void kernel_launch(void* const* d_in, const int* in_sizes, int n_in,
                              void* d_out, int out_size)
{
    const float* x      = (const float*)d_in[0];
    const float* in_w   = (const float*)d_in[1];
    const float* gn1_w  = (const float*)d_in[2];
    const float* gn1_b  = (const float*)d_in[3];
    const float* a_p    = (const float*)d_in[4];
    const float* b_p    = (const float*)d_in[5];
    const float* c_p    = (const float*)d_in[6];
    const float* d_p    = (const float*)d_in[7];
    const float* gate_w = (const float*)d_in[8];
    const float* gate_b = (const float*)d_in[9];
    const float* dw_w   = (const float*)d_in[10];
    const float* pw_w   = (const float*)d_in[11];
    const float* gn2_w  = (const float*)d_in[12];
    const float* gn2_b  = (const float*)d_in[13];
    float* out = (float*)d_out;

    float *buf0, *buf1, *buf2, *ps, *ps2;
    cudaGetSymbolAddress((void**)&buf0, g_buf0);
    cudaGetSymbolAddress((void**)&buf1, g_buf1);
    cudaGetSymbolAddress((void**)&buf2, g_buf2);
    cudaGetSymbolAddress((void**)&ps,  g_ps);
    cudaGetSymbolAddress((void**)&ps2, g_ps2);

    dim3 ggrid(HWP/128, CC/128, BB);   // (72, 2, 16)
    int elem4_blocks = (NTOT/4 + 255) / 256;
    int scanW_blocks = (BB*CC*HH + 255) / 256;
    int scanH_blocks = (BB*CC*(WW/4) + 255) / 256;
    int dw_blocks    = (NTOT + 255) / 256;

    // 1. xp_raw = in_w @ x   (+ fused GN1 partial stats)
    gemm_tc<0,1><<<ggrid, 256>>>(in_w, x, buf0, nullptr, ps, ps2);
    // 2. finalize gn1 stats
    finalize_stats<<<1, 256>>>(ps, ps2);
    // 3. xp = silu(gn1(xp_raw))
    gn_silu_kernel<<<elem4_blocks, 256>>>(buf0, buf1, gn1_w, gn1_b);
    // 4. gate = sigmoid(gate_w @ xp + gate_b)
    gemm_tc<1,0><<<ggrid, 256>>>(gate_w, buf1, buf0, gate_b, nullptr, nullptr);
    // 5. buf2 = lr + rl
    scanW_kernel<<<scanW_blocks, 256>>>(buf1, buf2, a_p, b_p, c_p, d_p);
    // 6. buf2 = 0.25*(lr+rl+tb+bt)*gate
    scanH_kernel<<<scanH_blocks, 256>>>(buf1, buf0, buf2, a_p, b_p, c_p, d_p);
    // 7. depthwise 3x3
    dw_kernel<<<dw_blocks, 256>>>(buf2, dw_w, buf1);
    // 8. out_raw = pw_w @ dw   (+ fused GN2 partial stats)
    gemm_tc<0,1><<<ggrid, 256>>>(pw_w, buf1, buf0, nullptr, ps, ps2);
    // 9. finalize gn2 stats
    finalize_stats<<<1, 256>>>(ps, ps2);
    // 10. out = silu(gn2(out_raw))
    gn_silu_kernel<<<elem4_blocks, 256>>>(buf0, out, gn2_w, gn2_b);
}

// round 12
// speedup vs baseline: 1.4851x; 1.3271x over previous
#include <cuda_runtime.h>
#include <math.h>
#include <stdint.h>

#define BB 16
#define CC 256
#define HH 96
#define WW 96
#define GG 16
#define CPG (CC/GG)          // 16
#define HWP (HH*WW)          // 9216
#define NTOT (BB*CC*HWP)     // 37748736
#define GROUPN (CPG*HWP)     // 147456
#define NBX 72               // pixel-tile blocks per (b, by)

// Scratch (device globals: no allocations allowed)
__device__ float g_buf0[NTOT];
__device__ float g_buf1[NTOT];
__device__ float g_buf2[NTOT];
__device__ float g_mean[BB*GG];
__device__ float g_rstd[BB*GG];
// Deterministic per-block GN partial sums: [b][by][gsub 8][bx 72]
__device__ float g_ps [BB*2*8*NBX];
__device__ float g_ps2[BB*2*8*NBX];

__device__ __forceinline__ float sigf(float x){ return 1.0f/(1.0f+expf(-x)); }

__device__ __forceinline__ uint32_t smem_u32(const void* p) {
    uint32_t a;
    asm("{ .reg .u64 t; cvta.to.shared.u64 t, %1; cvt.u32.u64 %0, t; }" : "=r"(a) : "l"(p));
    return a;
}
__device__ __forceinline__ void cp16(uint32_t dst, const float* src) {
    asm volatile("cp.async.cg.shared.global [%0], [%1], 16;" :: "r"(dst), "l"(src));
}

// ---------------------------------------------------------------------------
// Tensor-core GEMM (3xTF32 split precision, ~fp32 accuracy):
//   Y[b][o][p] = sum_c A[o][c] * X[b][c][p]
// cp.async double-buffered (R8-proven). Block 128x128, BK=16, 8 warps.
// ---------------------------------------------------------------------------
__device__ __forceinline__ void mma_tf32(float c[4], const uint32_t a[4], const uint32_t b[2]) {
    asm volatile(
        "mma.sync.aligned.m16n8k8.row.col.f32.tf32.tf32.f32 "
        "{%0,%1,%2,%3}, {%4,%5,%6,%7}, {%8,%9}, {%0,%1,%2,%3};\n"
        : "+f"(c[0]), "+f"(c[1]), "+f"(c[2]), "+f"(c[3])
        : "r"(a[0]), "r"(a[1]), "r"(a[2]), "r"(a[3]), "r"(b[0]), "r"(b[1]));
}
__device__ __forceinline__ void split_tf32(float x, uint32_t& hi, uint32_t& lo) {
    uint32_t xb = __float_as_uint(x) & 0xffffe000u;   // truncate to tf32
    hi = xb;
    lo = __float_as_uint(x - __uint_as_float(xb));    // residual (exact in fp32)
}

#define LDA 20
#define LDB 136
#define A_BUF (128*LDA)      // floats
#define B_BUF (16*LDB)

template<int EPI, int STATS>
__global__ __launch_bounds__(256, 2) void gemm_tc(
    const float* __restrict__ A, const float* __restrict__ X,
    float* __restrict__ Y, const float* __restrict__ bias,
    float* __restrict__ ps, float* __restrict__ ps2)
{
    __shared__ __align__(16) float AsT[2*A_BUF];   // [buf][m][k] pitch 20
    __shared__ __align__(16) float Bs [2*B_BUF];   // [buf][k][n] pitch 136
    __shared__ float sred[32], sred2[32];

    const int b   = blockIdx.z;
    const int om0 = blockIdx.y * 128;
    const int pn0 = blockIdx.x * 128;
    const int tid = threadIdx.x;
    const int lane = tid & 31;
    const int warp = tid >> 5;
    const int wm = (warp >> 2) * 64;
    const int wn = (warp & 3) * 32;
    const int r  = lane >> 2;
    const int q  = lane & 3;

    const float* Xb = X + (size_t)b * CC * HWP;
    float* Yb       = Y + (size_t)b * CC * HWP;

    const uint32_t a_smem = smem_u32(AsT);
    const uint32_t b_smem = smem_u32(Bs);

    const int am0 = (tid       ) >> 2, akq0 = ((tid       ) & 3) * 4;
    const int am1 = (tid + 256 ) >> 2, akq1 = ((tid + 256 ) & 3) * 4;
    const int bk0 = (tid       ) >> 5, bnq0 = ((tid       ) & 31) * 4;
    const int bk1 = (tid + 256 ) >> 5, bnq1 = ((tid + 256 ) & 31) * 4;

#define ISSUE_TILE(S, BUF) do { \
        int k0 = (S) * 16; \
        cp16(a_smem + (uint32_t)((BUF)*A_BUF + am0*LDA + akq0)*4, A + (size_t)(om0+am0)*CC + k0 + akq0); \
        cp16(a_smem + (uint32_t)((BUF)*A_BUF + am1*LDA + akq1)*4, A + (size_t)(om0+am1)*CC + k0 + akq1); \
        cp16(b_smem + (uint32_t)((BUF)*B_BUF + bk0*LDB + bnq0)*4, Xb + (size_t)(k0+bk0)*HWP + pn0 + bnq0); \
        cp16(b_smem + (uint32_t)((BUF)*B_BUF + bk1*LDB + bnq1)*4, Xb + (size_t)(k0+bk1)*HWP + pn0 + bnq1); \
        asm volatile("cp.async.commit_group;"); \
    } while (0)

    float acc[4][4][4];
#pragma unroll
    for (int mi = 0; mi < 4; mi++)
#pragma unroll
        for (int ni = 0; ni < 4; ni++)
#pragma unroll
            for (int k = 0; k < 4; k++) acc[mi][ni][k] = 0.f;

    ISSUE_TILE(0, 0);

    for (int s = 0; s < 16; s++) {
        const int buf = s & 1;
        if (s < 15) {
            ISSUE_TILE(s + 1, buf ^ 1);
            asm volatile("cp.async.wait_group 1;");
        } else {
            asm volatile("cp.async.wait_group 0;");
        }
        __syncthreads();

        const float* Ab = AsT + buf * A_BUF;
        const float* Bb = Bs  + buf * B_BUF;

#pragma unroll
        for (int ks = 0; ks < 16; ks += 8) {
            uint32_t ah[4][4], al[4][4];
#pragma unroll
            for (int mi = 0; mi < 4; mi++) {
                int m0 = wm + mi*16 + r;
                split_tf32(Ab[(m0    )*LDA + ks+q  ], ah[mi][0], al[mi][0]);
                split_tf32(Ab[(m0 + 8)*LDA + ks+q  ], ah[mi][1], al[mi][1]);
                split_tf32(Ab[(m0    )*LDA + ks+q+4], ah[mi][2], al[mi][2]);
                split_tf32(Ab[(m0 + 8)*LDA + ks+q+4], ah[mi][3], al[mi][3]);
            }
#pragma unroll
            for (int ni = 0; ni < 4; ni++) {
                int n0 = wn + ni*8 + r;
                uint32_t bh[2], bl[2];
                split_tf32(Bb[(ks+q  )*LDB + n0], bh[0], bl[0]);
                split_tf32(Bb[(ks+q+4)*LDB + n0], bh[1], bl[1]);
#pragma unroll
                for (int mi = 0; mi < 4; mi++) {
                    mma_tf32(acc[mi][ni], ah[mi], bh);   // hi*hi
                    mma_tf32(acc[mi][ni], al[mi], bh);   // lo*hi
                    mma_tf32(acc[mi][ni], ah[mi], bl);   // hi*lo
                }
            }
        }
        __syncthreads();
    }

#pragma unroll
    for (int mi = 0; mi < 4; mi++) {
        int o0 = om0 + wm + mi*16 + r;
        float bo0 = 0.f, bo1 = 0.f;
        if (EPI == 1) { bo0 = bias[o0]; bo1 = bias[o0 + 8]; }
#pragma unroll
        for (int ni = 0; ni < 4; ni++) {
            int p = pn0 + wn + ni*8 + 2*q;
            float2 v0, v1;
            v0.x = acc[mi][ni][0]; v0.y = acc[mi][ni][1];
            v1.x = acc[mi][ni][2]; v1.y = acc[mi][ni][3];
            if (EPI == 1) {
                v0.x = sigf(v0.x + bo0); v0.y = sigf(v0.y + bo0);
                v1.x = sigf(v1.x + bo1); v1.y = sigf(v1.y + bo1);
            }
            *(float2*)&Yb[(size_t)o0 * HWP + p]       = v0;
            *(float2*)&Yb[(size_t)(o0+8) * HWP + p]   = v1;
        }
    }

    if (STATS) {
#pragma unroll
        for (int mi = 0; mi < 4; mi++) {
            float s = 0.f, s2 = 0.f;
#pragma unroll
            for (int ni = 0; ni < 4; ni++)
#pragma unroll
                for (int k = 0; k < 4; k++) {
                    float v = acc[mi][ni][k];
                    s += v; s2 += v*v;
                }
#pragma unroll
            for (int m = 16; m > 0; m >>= 1) {
                s  += __shfl_xor_sync(0xffffffffu, s,  m);
                s2 += __shfl_xor_sync(0xffffffffu, s2, m);
            }
            if (lane == 0) { sred[warp*4 + mi] = s; sred2[warp*4 + mi] = s2; }
        }
        __syncthreads();
        if (tid < 8) {
            int wmIdx = tid >> 2, mi = tid & 3;
            float s = 0.f, s2 = 0.f;
#pragma unroll
            for (int nIdx = 0; nIdx < 4; nIdx++) {
                int w = wmIdx*4 + nIdx;
                s += sred[w*4 + mi]; s2 += sred2[w*4 + mi];
            }
            int gsub = wmIdx*4 + mi;
            int idx = ((b*2 + blockIdx.y)*8 + gsub)*NBX + blockIdx.x;
            ps[idx] = s; ps2[idx] = s2;
        }
    }
#undef ISSUE_TILE
}

// ---------------------------------------------------------------------------
// Finalize GN stats from per-block partials.
// ---------------------------------------------------------------------------
__global__ void finalize_stats(const float* __restrict__ ps, const float* __restrict__ ps2)
{
    int bg = threadIdx.x;
    int base = bg * NBX;
    float s = 0.f, s2 = 0.f;
    for (int i = 0; i < NBX; i++) { s += ps[base+i]; s2 += ps2[base+i]; }
    float mean = s / (float)GROUPN;
    float var  = s2 / (float)GROUPN - mean*mean;
    g_mean[bg] = mean;
    g_rstd[bg] = rsqrtf(var + 1e-5f);
}

// ---------------------------------------------------------------------------
// Apply group norm + SiLU (vectorized float4)
// ---------------------------------------------------------------------------
__global__ __launch_bounds__(256) void gn_silu_kernel(
    const float* __restrict__ in, float* __restrict__ out,
    const float* __restrict__ gw, const float* __restrict__ gb)
{
    int i4 = blockIdx.x * 256 + threadIdx.x;
    if (i4 >= NTOT/4) return;
    size_t idx = (size_t)i4 * 4;
    int c = (int)((idx / HWP) % CC);
    int b = (int)(idx / ((size_t)CC * HWP));
    int bg = b * GG + c / CPG;
    float m = g_mean[bg], rs = g_rstd[bg];
    float sw = gw[c] * rs;
    float sb = gb[c] - m * sw;
    float4 v = *(const float4*)&in[idx];
    float y;
    y = fmaf(v.x, sw, sb); v.x = y * sigf(y);
    y = fmaf(v.y, sw, sb); v.y = y * sigf(y);
    y = fmaf(v.z, sw, sb); v.z = y * sigf(y);
    y = fmaf(v.w, sw, sb); v.w = y * sigf(y);
    *(float4*)&out[idx] = v;
}

// ---------------------------------------------------------------------------
// Fused plane kernel: all 4 directional scans + 0.25*sum*gate + depthwise 3x3.
// One block per (b,c) plane (96x96 floats in smem, pitch 97 = conflict-free
// for both row and column walks). Reads xp + gate once, writes dw output once.
// ---------------------------------------------------------------------------
#define PITCH 97
#define PLANE (HH*PITCH)                 // 9312 floats
#define PLANE_SMEM (2*PLANE*4)           // 74496 bytes

__global__ __launch_bounds__(256) void plane_kernel(
    const float* __restrict__ xp, const float* __restrict__ gate,
    const float* __restrict__ dww, float* __restrict__ out,
    const float* __restrict__ a_p, const float* __restrict__ b_p,
    const float* __restrict__ c_p, const float* __restrict__ d_p)
{
    extern __shared__ float sm[];
    float* xs  = sm;           // xp plane
    float* acc = sm + PLANE;   // scan accumulator / fused plane

    const int bc  = blockIdx.x;       // b*CC + c
    const int c   = bc % CC;
    const int tid = threadIdx.x;
    const float* xpl = xp   + (size_t)bc * HWP;
    const float* gpl = gate + (size_t)bc * HWP;
    float*       opl = out  + (size_t)bc * HWP;

    // Load xp plane into smem (coalesced float4 reads, scalar smem stores)
    for (int i4 = tid; i4 < HWP/4; i4 += 256) {
        float4 v = *(const float4*)&xpl[i4*4];
        int row = i4 / (WW/4), col = (i4 % (WW/4)) * 4;
        float* d = &xs[row*PITCH + col];
        d[0]=v.x; d[1]=v.y; d[2]=v.z; d[3]=v.w;
    }
    __syncthreads();

    // W-direction scans: thread t = row t, lr forward then rl backward.
    if (tid < HH) {
        float a0 = sigf(a_p[c]),      b0 = b_p[c],      c0 = c_p[c],      d0 = d_p[c];
        float a1 = sigf(a_p[CC + c]), b1 = b_p[CC + c], c1 = c_p[CC + c], d1 = d_p[CC + c];
        float* xr = &xs[tid*PITCH];
        float* ar = &acc[tid*PITCH];
        float h = 0.f;
#pragma unroll 4
        for (int w = 0; w < WW; w++) {
            float x = xr[w];
            h = fmaf(a0, h, b0 * x);
            ar[w] = fmaf(c0, h, d0 * x);
        }
        h = 0.f;
#pragma unroll 4
        for (int w = WW-1; w >= 0; w--) {
            float x = xr[w];
            h = fmaf(a1, h, b1 * x);
            ar[w] += fmaf(c1, h, d1 * x);
        }
    }
    __syncthreads();

    // H-direction scans: thread t = column t, tb forward then bt backward.
    if (tid < WW) {
        float a2 = sigf(a_p[2*CC + c]), b2 = b_p[2*CC + c], c2 = c_p[2*CC + c], d2 = d_p[2*CC + c];
        float a3 = sigf(a_p[3*CC + c]), b3 = b_p[3*CC + c], c3 = c_p[3*CC + c], d3 = d_p[3*CC + c];
        float h = 0.f;
#pragma unroll 4
        for (int r = 0; r < HH; r++) {
            float x = xs[r*PITCH + tid];
            h = fmaf(a2, h, b2 * x);
            acc[r*PITCH + tid] += fmaf(c2, h, d2 * x);
        }
        h = 0.f;
#pragma unroll 4
        for (int r = HH-1; r >= 0; r--) {
            float x = xs[r*PITCH + tid];
            h = fmaf(a3, h, b3 * x);
            acc[r*PITCH + tid] += fmaf(c3, h, d3 * x);
        }
    }
    __syncthreads();

    // Gate combine: acc = 0.25 * acc * gate (gate streamed from gmem)
    for (int i4 = tid; i4 < HWP/4; i4 += 256) {
        float4 g = *(const float4*)&gpl[i4*4];
        int row = i4 / (WW/4), col = (i4 % (WW/4)) * 4;
        float* d = &acc[row*PITCH + col];
        d[0] = 0.25f * d[0] * g.x;
        d[1] = 0.25f * d[1] * g.y;
        d[2] = 0.25f * d[2] * g.z;
        d[3] = 0.25f * d[3] * g.w;
    }
    __syncthreads();

    // Depthwise 3x3 (SAME, zero pad) from smem -> gmem
    const float* pk = dww + c * 9;
    float k0 = pk[0], k1 = pk[1], k2 = pk[2];
    float k3 = pk[3], k4 = pk[4], k5 = pk[5];
    float k6 = pk[6], k7 = pk[7], k8 = pk[8];
    for (int idx = tid; idx < HWP; idx += 256) {
        int row = idx / WW, col = idx % WW;
        float s = 0.f;
        if (row > 0) {
            const float* rr = &acc[(row-1)*PITCH];
            if (col > 0)    s = fmaf(rr[col-1], k0, s);
                            s = fmaf(rr[col],   k1, s);
            if (col < WW-1) s = fmaf(rr[col+1], k2, s);
        }
        {
            const float* rr = &acc[row*PITCH];
            if (col > 0)    s = fmaf(rr[col-1], k3, s);
                            s = fmaf(rr[col],   k4, s);
            if (col < WW-1) s = fmaf(rr[col+1], k5, s);
        }
        if (row < HH-1) {
            const float* rr = &acc[(row+1)*PITCH];
            if (col > 0)    s = fmaf(rr[col-1], k6, s);
                            s = fmaf(rr[col],   k7, s);
            if (col < WW-1) s = fmaf(rr[col+1], k8, s);
        }
        opl[idx] = s;
    }
}

// ---------------------------------------------------------------------------
extern "C" void kernel_launch(void* const* d_in, const int* in_sizes, int n_in,
                              void* d_out, int out_size)
{
    const float* x      = (const float*)d_in[0];
    const float* in_w   = (const float*)d_in[1];
    const float* gn1_w  = (const float*)d_in[2];
    const float* gn1_b  = (const float*)d_in[3];
    const float* a_p    = (const float*)d_in[4];
    const float* b_p    = (const float*)d_in[5];
    const float* c_p    = (const float*)d_in[6];
    const float* d_p    = (const float*)d_in[7];
    const float* gate_w = (const float*)d_in[8];
    const float* gate_b = (const float*)d_in[9];
    const float* dw_w   = (const float*)d_in[10];
    const float* pw_w   = (const float*)d_in[11];
    const float* gn2_w  = (const float*)d_in[12];
    const float* gn2_b  = (const float*)d_in[13];
    float* out = (float*)d_out;

    float *buf0, *buf1, *buf2, *ps, *ps2;
    cudaGetSymbolAddress((void**)&buf0, g_buf0);
    cudaGetSymbolAddress((void**)&buf1, g_buf1);
    cudaGetSymbolAddress((void**)&buf2, g_buf2);
    cudaGetSymbolAddress((void**)&ps,  g_ps);
    cudaGetSymbolAddress((void**)&ps2, g_ps2);

    cudaFuncSetAttribute(plane_kernel, cudaFuncAttributeMaxDynamicSharedMemorySize, PLANE_SMEM);

    dim3 ggrid(HWP/128, CC/128, BB);   // (72, 2, 16)
    int elem4_blocks = (NTOT/4 + 255) / 256;

    // 1. xp_raw = in_w @ x   (+ fused GN1 partial stats)
    gemm_tc<0,1><<<ggrid, 256>>>(in_w, x, buf0, nullptr, ps, ps2);
    // 2. finalize gn1 stats
    finalize_stats<<<1, 256>>>(ps, ps2);
    // 3. xp = silu(gn1(xp_raw))
    gn_silu_kernel<<<elem4_blocks, 256>>>(buf0, buf1, gn1_w, gn1_b);
    // 4. gate = sigmoid(gate_w @ xp + gate_b)
    gemm_tc<1,0><<<ggrid, 256>>>(gate_w, buf1, buf0, gate_b, nullptr, nullptr);
    // 5. fused: 4 scans + gate combine + depthwise 3x3  (buf1,buf0 -> buf2)
    plane_kernel<<<BB*CC, 256, PLANE_SMEM>>>(buf1, buf0, dw_w, buf2,
                                             a_p, b_p, c_p, d_p);
    // 6. out_raw = pw_w @ dw   (+ fused GN2 partial stats)
    gemm_tc<0,1><<<ggrid, 256>>>(pw_w, buf2, buf0, nullptr, ps, ps2);
    // 7. finalize gn2 stats
    finalize_stats<<<1, 256>>>(ps, ps2);
    // 8. out = silu(gn2(out_raw))
    gn_silu_kernel<<<elem4_blocks, 256>>>(buf0, out, gn2_w, gn2_b);
}

// round 13
// speedup vs baseline: 1.8165x; 1.2232x over previous
#include <cuda_runtime.h>
#include <cuda_bf16.h>
#include <math.h>
#include <stdint.h>

#define BB 16
#define CC 256
#define HH 96
#define WW 96
#define GG 16
#define CPG (CC/GG)          // 16
#define HWP (HH*WW)          // 9216
#define NTOT (BB*CC*HWP)     // 37748736
#define GROUPN (CPG*HWP)     // 147456
#define NBX 72               // pixel-tile blocks per (b, by)
#define KPC (CC/2)           // 128 channel pairs
#define PLANE_WORDS ((size_t)KPC*HWP)   // packed words per batch

// Scratch (device globals: no allocations allowed)
__device__ float g_buf0[NTOT];
__device__ float g_buf1[NTOT];
__device__ float g_buf2[NTOT];
__device__ uint32_t g_h0[NTOT/2], g_l0[NTOT/2];   // packed bf16 pairs: x, then dw
__device__ uint32_t g_h1[NTOT/2], g_l1[NTOT/2];   // packed bf16 pairs: xp
__device__ uint32_t g_wh[3*CC*KPC], g_wl[3*CC*KPC];
__device__ float g_mean[BB*GG];
__device__ float g_rstd[BB*GG];
__device__ float g_ps [BB*2*8*NBX];
__device__ float g_ps2[BB*2*8*NBX];

__device__ __forceinline__ float sigf(float x){ return 1.0f/(1.0f+expf(-x)); }

__device__ __forceinline__ uint32_t smem_u32(const void* p) {
    uint32_t a;
    asm("{ .reg .u64 t; cvta.to.shared.u64 t, %1; cvt.u32.u64 %0, t; }" : "=r"(a) : "l"(p));
    return a;
}
__device__ __forceinline__ void cp16(uint32_t dst, const void* src) {
    asm volatile("cp.async.cg.shared.global [%0], [%1], 16;" :: "r"(dst), "l"(src));
}

// Split x into bf16 hi + bf16 lo; pack two k-adjacent values per b32 word
// (low half = even k), matching the m16n8k16 fragment element order.
__device__ __forceinline__ void bfsplit2(float a, float b, uint32_t& hw, uint32_t& lw){
    __nv_bfloat16 ah = __float2bfloat16_rn(a), bh = __float2bfloat16_rn(b);
    float ar = a - __bfloat162float(ah);
    float br = b - __bfloat162float(bh);
    __nv_bfloat16 al = __float2bfloat16_rn(ar), bl = __float2bfloat16_rn(br);
    hw = (uint32_t)__bfloat16_as_ushort(ah) | ((uint32_t)__bfloat16_as_ushort(bh) << 16);
    lw = (uint32_t)__bfloat16_as_ushort(al) | ((uint32_t)__bfloat16_as_ushort(bl) << 16);
}

__device__ __forceinline__ void mma_bf16(float c[4], const uint32_t a[4], uint32_t b0, uint32_t b1){
    asm volatile(
        "mma.sync.aligned.m16n8k16.row.col.f32.bf16.bf16.f32 "
        "{%0,%1,%2,%3}, {%4,%5,%6,%7}, {%8,%9}, {%0,%1,%2,%3};\n"
        : "+f"(c[0]), "+f"(c[1]), "+f"(c[2]), "+f"(c[3])
        : "r"(a[0]), "r"(a[1]), "r"(a[2]), "r"(a[3]), "r"(b0), "r"(b1));
}

// ---------------------------------------------------------------------------
// Pre-split kernels
// ---------------------------------------------------------------------------
__global__ void split_w_kernel(const float* __restrict__ w0, const float* __restrict__ w1,
                               const float* __restrict__ w2)
{
    int t = blockIdx.x * 256 + threadIdx.x;          // over 3*CC*KPC = 98304
    if (t >= 3*CC*KPC) return;
    int wsel = t / (CC*KPC);
    int rem  = t % (CC*KPC);
    int o = rem / KPC, kp = rem % KPC;
    const float* W = (wsel == 0) ? w0 : ((wsel == 1) ? w1 : w2);
    bfsplit2(W[o*CC + 2*kp], W[o*CC + 2*kp + 1], g_wh[t], g_wl[t]);
}

__global__ void split_x_kernel(const float* __restrict__ x)
{
    size_t i4 = (size_t)blockIdx.x * 256 + threadIdx.x;   // groups of 4 words
    if (i4 >= (size_t)(NTOT/2)/4) return;
    size_t w0 = i4 * 4;
    int b  = (int)(w0 / PLANE_WORDS);
    size_t rem = w0 % PLANE_WORDS;
    int kp = (int)(rem / HWP);
    int p  = (int)(rem % HWP);
    const float* x0 = x + (size_t)b*CC*HWP + (size_t)(2*kp)*HWP + p;
    float4 v0 = *(const float4*)x0;
    float4 v1 = *(const float4*)(x0 + HWP);
    uint4 h, l;
    bfsplit2(v0.x, v1.x, h.x, l.x);
    bfsplit2(v0.y, v1.y, h.y, l.y);
    bfsplit2(v0.z, v1.z, h.z, l.z);
    bfsplit2(v0.w, v1.w, h.w, l.w);
    *(uint4*)&g_h0[w0] = h;
    *(uint4*)&g_l0[w0] = l;
}

// ---------------------------------------------------------------------------
// Tensor-core GEMM, bf16 3-split (hi*hi + lo*hi + hi*lo), m16n8k16.
//   Y[b][o][p] = sum_c W[o][c] * X[b][c][p]
// Operands pre-split + pre-packed in gmem -> cp.async straight in, no ALU.
// Block 128x128, BK=16 (8 packed words), 8 warps (2M x 4N), warp 64x32.
// ---------------------------------------------------------------------------
#define LDAW 12
#define LDBW 136
#define AW_BUF (128*LDAW)    // 1536 words
#define BW_BUF (8*LDBW)      // 1088 words

template<int EPI, int STATS>
__global__ __launch_bounds__(256, 2) void gemm_bf3(
    const uint32_t* __restrict__ Ah_g, const uint32_t* __restrict__ Al_g,
    const uint32_t* __restrict__ Bh_g, const uint32_t* __restrict__ Bl_g,
    float* __restrict__ Y, const float* __restrict__ bias,
    float* __restrict__ ps, float* __restrict__ ps2)
{
    __shared__ __align__(16) uint32_t sAh[2*AW_BUF], sAl[2*AW_BUF];
    __shared__ __align__(16) uint32_t sBh[2*BW_BUF], sBl[2*BW_BUF];
    __shared__ float sred[32], sred2[32];

    const int b   = blockIdx.z;
    const int om0 = blockIdx.y * 128;
    const int pn0 = blockIdx.x * 128;
    const int tid = threadIdx.x;
    const int lane = tid & 31;
    const int warp = tid >> 5;
    const int wm = (warp >> 2) * 64;
    const int wn = (warp & 3) * 32;
    const int r  = lane >> 2;
    const int q  = lane & 3;

    const uint32_t* Bhb = Bh_g + (size_t)b * PLANE_WORDS;
    const uint32_t* Blb = Bl_g + (size_t)b * PLANE_WORDS;
    float* Yb = Y + (size_t)b * CC * HWP;

    const uint32_t ah_s = smem_u32(sAh), al_s = smem_u32(sAl);
    const uint32_t bh_s = smem_u32(sBh), bl_s = smem_u32(sBl);

    const int arow = tid >> 1, ahw = (tid & 1) * 4;
    const int bkp  = tid >> 5, bn4 = (tid & 31) * 4;

#define ISSUE_TILE(S, BUF) do { \
        int kcw = (S) * 8; \
        size_t asrc = (size_t)(om0 + arow) * KPC + kcw + ahw; \
        uint32_t adst = (uint32_t)((BUF)*AW_BUF + arow*LDAW + ahw) * 4; \
        cp16(ah_s + adst, Ah_g + asrc); \
        cp16(al_s + adst, Al_g + asrc); \
        size_t bsrc = (size_t)(kcw + bkp) * HWP + pn0 + bn4; \
        uint32_t bdst = (uint32_t)((BUF)*BW_BUF + bkp*LDBW + bn4) * 4; \
        cp16(bh_s + bdst, Bhb + bsrc); \
        cp16(bl_s + bdst, Blb + bsrc); \
        asm volatile("cp.async.commit_group;"); \
    } while (0)

    float acc[4][4][4];
#pragma unroll
    for (int mi = 0; mi < 4; mi++)
#pragma unroll
        for (int ni = 0; ni < 4; ni++)
#pragma unroll
            for (int k = 0; k < 4; k++) acc[mi][ni][k] = 0.f;

    ISSUE_TILE(0, 0);

    for (int s = 0; s < 16; s++) {
        const int buf = s & 1;
        if (s < 15) {
            ISSUE_TILE(s + 1, buf ^ 1);
            asm volatile("cp.async.wait_group 1;");
        } else {
            asm volatile("cp.async.wait_group 0;");
        }
        __syncthreads();

        const uint32_t* Abh = sAh + buf*AW_BUF;
        const uint32_t* Abl = sAl + buf*AW_BUF;
        const uint32_t* Bbh = sBh + buf*BW_BUF;
        const uint32_t* Bbl = sBl + buf*BW_BUF;

        uint32_t ah[4][4], al[4][4];
#pragma unroll
        for (int mi = 0; mi < 4; mi++) {
            int base = (wm + mi*16 + r) * LDAW;
            ah[mi][0] = Abh[base + q];
            ah[mi][1] = Abh[base + 8*LDAW + q];
            ah[mi][2] = Abh[base + q + 4];
            ah[mi][3] = Abh[base + 8*LDAW + q + 4];
            al[mi][0] = Abl[base + q];
            al[mi][1] = Abl[base + 8*LDAW + q];
            al[mi][2] = Abl[base + q + 4];
            al[mi][3] = Abl[base + 8*LDAW + q + 4];
        }
#pragma unroll
        for (int ni = 0; ni < 4; ni++) {
            int n0 = wn + ni*8 + r;
            uint32_t bh0 = Bbh[q*LDBW + n0], bh1 = Bbh[(q+4)*LDBW + n0];
            uint32_t bl0 = Bbl[q*LDBW + n0], bl1 = Bbl[(q+4)*LDBW + n0];
#pragma unroll
            for (int mi = 0; mi < 4; mi++) {
                mma_bf16(acc[mi][ni], ah[mi], bh0, bh1);   // hi*hi
                mma_bf16(acc[mi][ni], al[mi], bh0, bh1);   // lo*hi
                mma_bf16(acc[mi][ni], ah[mi], bl0, bl1);   // hi*lo
            }
        }
        __syncthreads();
    }

    // Epilogue. c0:(r, 2q) c1:(r, 2q+1) c2:(r+8, 2q) c3:(r+8, 2q+1)
#pragma unroll
    for (int mi = 0; mi < 4; mi++) {
        int o0 = om0 + wm + mi*16 + r;
        float bo0 = 0.f, bo1 = 0.f;
        if (EPI == 1) { bo0 = bias[o0]; bo1 = bias[o0 + 8]; }
#pragma unroll
        for (int ni = 0; ni < 4; ni++) {
            int p = pn0 + wn + ni*8 + 2*q;
            float2 v0, v1;
            v0.x = acc[mi][ni][0]; v0.y = acc[mi][ni][1];
            v1.x = acc[mi][ni][2]; v1.y = acc[mi][ni][3];
            if (EPI == 1) {
                v0.x = sigf(v0.x + bo0); v0.y = sigf(v0.y + bo0);
                v1.x = sigf(v1.x + bo1); v1.y = sigf(v1.y + bo1);
            }
            *(float2*)&Yb[(size_t)o0 * HWP + p]     = v0;
            *(float2*)&Yb[(size_t)(o0+8) * HWP + p] = v1;
        }
    }

    if (STATS) {
#pragma unroll
        for (int mi = 0; mi < 4; mi++) {
            float s = 0.f, s2 = 0.f;
#pragma unroll
            for (int ni = 0; ni < 4; ni++)
#pragma unroll
                for (int k = 0; k < 4; k++) {
                    float v = acc[mi][ni][k];
                    s += v; s2 += v*v;
                }
#pragma unroll
            for (int m = 16; m > 0; m >>= 1) {
                s  += __shfl_xor_sync(0xffffffffu, s,  m);
                s2 += __shfl_xor_sync(0xffffffffu, s2, m);
            }
            if (lane == 0) { sred[warp*4 + mi] = s; sred2[warp*4 + mi] = s2; }
        }
        __syncthreads();
        if (tid < 8) {
            int wmIdx = tid >> 2, mi = tid & 3;
            float s = 0.f, s2 = 0.f;
#pragma unroll
            for (int nIdx = 0; nIdx < 4; nIdx++) {
                int w = wmIdx*4 + nIdx;
                s += sred[w*4 + mi]; s2 += sred2[w*4 + mi];
            }
            int gsub = wmIdx*4 + mi;
            int idx = ((b*2 + blockIdx.y)*8 + gsub)*NBX + blockIdx.x;
            ps[idx] = s; ps2[idx] = s2;
        }
    }
#undef ISSUE_TILE
}

// ---------------------------------------------------------------------------
// Finalize GN stats from per-block partials.
// ---------------------------------------------------------------------------
__global__ void finalize_stats(const float* __restrict__ ps, const float* __restrict__ ps2)
{
    int bg = threadIdx.x;
    int base = bg * NBX;
    float s = 0.f, s2 = 0.f;
    for (int i = 0; i < NBX; i++) { s += ps[base+i]; s2 += ps2[base+i]; }
    float mean = s / (float)GROUPN;
    float var  = s2 / (float)GROUPN - mean*mean;
    g_mean[bg] = mean;
    g_rstd[bg] = rsqrtf(var + 1e-5f);
}

// ---------------------------------------------------------------------------
// GroupNorm + SiLU; PACK=1 also emits packed bf16 hi/lo for the next GEMM.
// Processes a channel PAIR x 4 pixels per thread.
// ---------------------------------------------------------------------------
template<int PACK>
__global__ __launch_bounds__(256) void gn_silu_k(
    const float* __restrict__ in, float* __restrict__ outf,
    const float* __restrict__ gw, const float* __restrict__ gb,
    uint32_t* __restrict__ oh, uint32_t* __restrict__ ol)
{
    size_t i4 = (size_t)blockIdx.x * 256 + threadIdx.x;
    if (i4 >= (size_t)(NTOT/2)/4) return;
    size_t w0 = i4 * 4;
    int b  = (int)(w0 / PLANE_WORDS);
    size_t rem = w0 % PLANE_WORDS;
    int kp = (int)(rem / HWP);
    int p  = (int)(rem % HWP);
    int c0 = 2*kp;
    int bg = b * GG + c0 / CPG;
    float m = g_mean[bg], rs = g_rstd[bg];
    float sw0 = gw[c0] * rs,   sb0 = gb[c0]   - m * sw0;
    float sw1 = gw[c0+1] * rs, sb1 = gb[c0+1] - m * sw1;

    size_t fidx = (size_t)b*CC*HWP + (size_t)c0*HWP + p;
    float4 v0 = *(const float4*)&in[fidx];
    float4 v1 = *(const float4*)&in[fidx + HWP];
    float y;
    y = fmaf(v0.x, sw0, sb0); v0.x = y * sigf(y);
    y = fmaf(v0.y, sw0, sb0); v0.y = y * sigf(y);
    y = fmaf(v0.z, sw0, sb0); v0.z = y * sigf(y);
    y = fmaf(v0.w, sw0, sb0); v0.w = y * sigf(y);
    y = fmaf(v1.x, sw1, sb1); v1.x = y * sigf(y);
    y = fmaf(v1.y, sw1, sb1); v1.y = y * sigf(y);
    y = fmaf(v1.z, sw1, sb1); v1.z = y * sigf(y);
    y = fmaf(v1.w, sw1, sb1); v1.w = y * sigf(y);
    *(float4*)&outf[fidx]       = v0;
    *(float4*)&outf[fidx + HWP] = v1;

    if (PACK) {
        uint4 h, l;
        bfsplit2(v0.x, v1.x, h.x, l.x);
        bfsplit2(v0.y, v1.y, h.y, l.y);
        bfsplit2(v0.z, v1.z, h.z, l.z);
        bfsplit2(v0.w, v1.w, h.w, l.w);
        *(uint4*)&oh[w0] = h;
        *(uint4*)&ol[w0] = l;
    }
}

// ---------------------------------------------------------------------------
// Fused plane kernel: 4 scans + 0.25*sum*gate + depthwise 3x3.
// Output: packed bf16 hi/lo (uint16 interleaved stores into pair layout).
// ---------------------------------------------------------------------------
#define PITCH 97
#define PLANE (HH*PITCH)
#define PLANE_SMEM (2*PLANE*4)

__global__ __launch_bounds__(256) void plane_kernel(
    const float* __restrict__ xp, const float* __restrict__ gate,
    const float* __restrict__ dww,
    uint32_t* __restrict__ dwh, uint32_t* __restrict__ dwl,
    const float* __restrict__ a_p, const float* __restrict__ b_p,
    const float* __restrict__ c_p, const float* __restrict__ d_p)
{
    extern __shared__ float sm[];
    float* xs  = sm;
    float* acc = sm + PLANE;

    const int bc  = blockIdx.x;
    const int b   = bc / CC;
    const int c   = bc % CC;
    const int tid = threadIdx.x;
    const float* xpl = xp   + (size_t)bc * HWP;
    const float* gpl = gate + (size_t)bc * HWP;

    for (int i4 = tid; i4 < HWP/4; i4 += 256) {
        float4 v = *(const float4*)&xpl[i4*4];
        int row = i4 / (WW/4), col = (i4 % (WW/4)) * 4;
        float* d = &xs[row*PITCH + col];
        d[0]=v.x; d[1]=v.y; d[2]=v.z; d[3]=v.w;
    }
    __syncthreads();

    if (tid < HH) {
        float a0 = sigf(a_p[c]),      b0 = b_p[c],      c0 = c_p[c],      d0 = d_p[c];
        float a1 = sigf(a_p[CC + c]), b1 = b_p[CC + c], c1 = c_p[CC + c], d1 = d_p[CC + c];
        float* xr = &xs[tid*PITCH];
        float* ar = &acc[tid*PITCH];
        float h = 0.f;
#pragma unroll 4
        for (int w = 0; w < WW; w++) {
            float x = xr[w];
            h = fmaf(a0, h, b0 * x);
            ar[w] = fmaf(c0, h, d0 * x);
        }
        h = 0.f;
#pragma unroll 4
        for (int w = WW-1; w >= 0; w--) {
            float x = xr[w];
            h = fmaf(a1, h, b1 * x);
            ar[w] += fmaf(c1, h, d1 * x);
        }
    }
    __syncthreads();

    if (tid < WW) {
        float a2 = sigf(a_p[2*CC + c]), b2 = b_p[2*CC + c], c2 = c_p[2*CC + c], d2 = d_p[2*CC + c];
        float a3 = sigf(a_p[3*CC + c]), b3 = b_p[3*CC + c], c3 = c_p[3*CC + c], d3 = d_p[3*CC + c];
        float h = 0.f;
#pragma unroll 4
        for (int r = 0; r < HH; r++) {
            float x = xs[r*PITCH + tid];
            h = fmaf(a2, h, b2 * x);
            acc[r*PITCH + tid] += fmaf(c2, h, d2 * x);
        }
        h = 0.f;
#pragma unroll 4
        for (int r = HH-1; r >= 0; r--) {
            float x = xs[r*PITCH + tid];
            h = fmaf(a3, h, b3 * x);
            acc[r*PITCH + tid] += fmaf(c3, h, d3 * x);
        }
    }
    __syncthreads();

    for (int i4 = tid; i4 < HWP/4; i4 += 256) {
        float4 g = *(const float4*)&gpl[i4*4];
        int row = i4 / (WW/4), col = (i4 % (WW/4)) * 4;
        float* d = &acc[row*PITCH + col];
        d[0] = 0.25f * d[0] * g.x;
        d[1] = 0.25f * d[1] * g.y;
        d[2] = 0.25f * d[2] * g.z;
        d[3] = 0.25f * d[3] * g.w;
    }
    __syncthreads();

    // Depthwise 3x3 from smem -> packed bf16 hi/lo gmem (uint16 interleave)
    const float* pk = dww + c * 9;
    float k0 = pk[0], k1 = pk[1], k2 = pk[2];
    float k3 = pk[3], k4 = pk[4], k5 = pk[5];
    float k6 = pk[6], k7 = pk[7], k8 = pk[8];
    uint16_t* oh = (uint16_t*)dwh;
    uint16_t* ol = (uint16_t*)dwl;
    size_t base16 = ((size_t)b*PLANE_WORDS + (size_t)(c >> 1)*HWP)*2 + (c & 1);
    for (int idx = tid; idx < HWP; idx += 256) {
        int row = idx / WW, col = idx % WW;
        float s = 0.f;
        if (row > 0) {
            const float* rr = &acc[(row-1)*PITCH];
            if (col > 0)    s = fmaf(rr[col-1], k0, s);
                            s = fmaf(rr[col],   k1, s);
            if (col < WW-1) s = fmaf(rr[col+1], k2, s);
        }
        {
            const float* rr = &acc[row*PITCH];
            if (col > 0)    s = fmaf(rr[col-1], k3, s);
                            s = fmaf(rr[col],   k4, s);
            if (col < WW-1) s = fmaf(rr[col+1], k5, s);
        }
        if (row < HH-1) {
            const float* rr = &acc[(row+1)*PITCH];
            if (col > 0)    s = fmaf(rr[col-1], k6, s);
                            s = fmaf(rr[col],   k7, s);
            if (col < WW-1) s = fmaf(rr[col+1], k8, s);
        }
        __nv_bfloat16 hb = __float2bfloat16_rn(s);
        float rsd = s - __bfloat162float(hb);
        oh[base16 + 2*(size_t)idx] = __bfloat16_as_ushort(hb);
        ol[base16 + 2*(size_t)idx] = __bfloat16_as_ushort(__float2bfloat16_rn(rsd));
    }
}

// ---------------------------------------------------------------------------
extern "C" void kernel_launch(void* const* d_in, const int* in_sizes, int n_in,
                              void* d_out, int out_size)
{
    const float* x      = (const float*)d_in[0];
    const float* in_w   = (const float*)d_in[1];
    const float* gn1_w  = (const float*)d_in[2];
    const float* gn1_b  = (const float*)d_in[3];
    const float* a_p    = (const float*)d_in[4];
    const float* b_p    = (const float*)d_in[5];
    const float* c_p    = (const float*)d_in[6];
    const float* d_p    = (const float*)d_in[7];
    const float* gate_w = (const float*)d_in[8];
    const float* gate_b = (const float*)d_in[9];
    const float* dw_w   = (const float*)d_in[10];
    const float* pw_w   = (const float*)d_in[11];
    const float* gn2_w  = (const float*)d_in[12];
    const float* gn2_b  = (const float*)d_in[13];
    float* out = (float*)d_out;

    float *buf0, *buf1, *buf2, *ps, *ps2;
    uint32_t *h0, *l0, *h1, *l1, *wh, *wl;
    cudaGetSymbolAddress((void**)&buf0, g_buf0);
    cudaGetSymbolAddress((void**)&buf1, g_buf1);
    cudaGetSymbolAddress((void**)&buf2, g_buf2);
    cudaGetSymbolAddress((void**)&ps,  g_ps);
    cudaGetSymbolAddress((void**)&ps2, g_ps2);
    cudaGetSymbolAddress((void**)&h0, g_h0);
    cudaGetSymbolAddress((void**)&l0, g_l0);
    cudaGetSymbolAddress((void**)&h1, g_h1);
    cudaGetSymbolAddress((void**)&l1, g_l1);
    cudaGetSymbolAddress((void**)&wh, g_wh);
    cudaGetSymbolAddress((void**)&wl, g_wl);

    cudaFuncSetAttribute(plane_kernel, cudaFuncAttributeMaxDynamicSharedMemorySize, PLANE_SMEM);

    dim3 ggrid(HWP/128, CC/128, BB);               // (72, 2, 16)
    int pair4_blocks = (int)(((size_t)(NTOT/2)/4 + 255) / 256);  // 18432

    // 0. pre-split weights + input
    split_w_kernel<<<(3*CC*KPC + 255)/256, 256>>>(in_w, gate_w, pw_w);
    split_x_kernel<<<pair4_blocks, 256>>>(x);
    // 1. xp_raw = in_w @ x   (+ fused GN1 partial stats)
    gemm_bf3<0,1><<<ggrid, 256>>>(wh, wl, h0, l0, buf0, nullptr, ps, ps2);
    // 2. finalize gn1 stats
    finalize_stats<<<1, 256>>>(ps, ps2);
    // 3. xp = silu(gn1(xp_raw))  fp32 + packed bf16 hi/lo
    gn_silu_k<1><<<pair4_blocks, 256>>>(buf0, buf1, gn1_w, gn1_b, h1, l1);
    // 4. gate = sigmoid(gate_w @ xp + gate_b)
    gemm_bf3<1,0><<<ggrid, 256>>>(wh + CC*KPC, wl + CC*KPC, h1, l1, buf2, gate_b, nullptr, nullptr);
    // 5. fused scans + gate + depthwise -> packed bf16 hi/lo (reuse h0/l0)
    plane_kernel<<<BB*CC, 256, PLANE_SMEM>>>(buf1, buf2, dw_w, h0, l0, a_p, b_p, c_p, d_p);
    // 6. out_raw = pw_w @ dw   (+ fused GN2 partial stats)
    gemm_bf3<0,1><<<ggrid, 256>>>(wh + 2*CC*KPC, wl + 2*CC*KPC, h0, l0, buf0, nullptr, ps, ps2);
    // 7. finalize gn2 stats
    finalize_stats<<<1, 256>>>(ps, ps2);
    // 8. out = silu(gn2(out_raw))
    gn_silu_k<0><<<pair4_blocks, 256>>>(buf0, out, gn2_w, gn2_b, nullptr, nullptr);
}

// round 15
// speedup vs baseline: 2.0015x; 1.1018x over previous
#include <cuda_runtime.h>
#include <cuda_bf16.h>
#include <math.h>
#include <stdint.h>

#define BB 16
#define CC 256
#define HH 96
#define WW 96
#define GG 16
#define CPG (CC/GG)          // 16
#define HWP (HH*WW)          // 9216
#define NTOT (BB*CC*HWP)     // 37748736
#define GROUPN (CPG*HWP)     // 147456
#define NBX 72               // pixel-tile blocks per (b, by)
#define KPC (CC/2)           // 128 channel pairs
#define PLANE_WORDS ((size_t)KPC*HWP)   // packed words per batch

// Scratch (device globals: no allocations allowed)
__device__ float g_buf0[NTOT];
__device__ float g_buf1[NTOT];
__device__ float g_buf2[NTOT];
__device__ uint32_t g_h0[NTOT/2], g_l0[NTOT/2];   // packed bf16 pairs: x, then dw
__device__ uint32_t g_h1[NTOT/2], g_l1[NTOT/2];   // packed bf16 pairs: xp
__device__ uint32_t g_wh[3*CC*KPC], g_wl[3*CC*KPC];  // fragment-ordered weights
__device__ float g_mean[BB*GG];
__device__ float g_rstd[BB*GG];
__device__ float g_ps [BB*2*8*NBX];
__device__ float g_ps2[BB*2*8*NBX];

__device__ __forceinline__ float sigf(float x){ return 1.0f/(1.0f+expf(-x)); }

__device__ __forceinline__ uint32_t smem_u32(const void* p) {
    uint32_t a;
    asm("{ .reg .u64 t; cvta.to.shared.u64 t, %1; cvt.u32.u64 %0, t; }" : "=r"(a) : "l"(p));
    return a;
}
__device__ __forceinline__ void cp16(uint32_t dst, const void* src) {
    asm volatile("cp.async.cg.shared.global [%0], [%1], 16;" :: "r"(dst), "l"(src));
}

// Split into bf16 hi + bf16 lo; pack two k-adjacent values per b32 word
// (low half = even k), matching the m16n8k16 fragment element order.
__device__ __forceinline__ void bfsplit2(float a, float b, uint32_t& hw, uint32_t& lw){
    __nv_bfloat16 ah = __float2bfloat16_rn(a), bh = __float2bfloat16_rn(b);
    float ar = a - __bfloat162float(ah);
    float br = b - __bfloat162float(bh);
    __nv_bfloat16 al = __float2bfloat16_rn(ar), bl = __float2bfloat16_rn(br);
    hw = (uint32_t)__bfloat16_as_ushort(ah) | ((uint32_t)__bfloat16_as_ushort(bh) << 16);
    lw = (uint32_t)__bfloat16_as_ushort(al) | ((uint32_t)__bfloat16_as_ushort(bl) << 16);
}

__device__ __forceinline__ void mma_bf16(float c[4], const uint32_t a[4], uint32_t b0, uint32_t b1){
    asm volatile(
        "mma.sync.aligned.m16n8k16.row.col.f32.bf16.bf16.f32 "
        "{%0,%1,%2,%3}, {%4,%5,%6,%7}, {%8,%9}, {%0,%1,%2,%3};\n"
        : "+f"(c[0]), "+f"(c[1]), "+f"(c[2]), "+f"(c[3])
        : "r"(a[0]), "r"(a[1]), "r"(a[2]), "r"(a[3]), "r"(b0), "r"(b1));
}

// ---------------------------------------------------------------------------
// Pre-split kernels. Weights go to FRAGMENT order:
//   index = ((ktile*16 + rowgroup)*32 + (r*4 + q))*4 + w
//   w: 0=(row g*16+r, kw ktile*8+q) 1=(+8 row) 2=(kw +4) 3=(+8,+4)
// so one uint4 LDS = one full m16n8k16 A fragment.
// ---------------------------------------------------------------------------
__global__ void split_w_kernel(const float* __restrict__ w0, const float* __restrict__ w1,
                               const float* __restrict__ w2)
{
    int t = blockIdx.x * 256 + threadIdx.x;          // over 3*CC*KPC = 98304
    if (t >= 3*CC*KPC) return;
    int wsel = t / (CC*KPC);
    int i    = t % (CC*KPC);
    int w    = i & 3;
    int lane = (i >> 2) & 31;
    int g    = (i >> 7) & 15;
    int tt   = i >> 11;
    int q = lane & 3, r = lane >> 2;
    int kh = w >> 1, half = w & 1;
    int o  = g*16 + half*8 + r;
    int kw = tt*8 + kh*4 + q;
    const float* W = (wsel == 0) ? w0 : ((wsel == 1) ? w1 : w2);
    bfsplit2(W[o*CC + 2*kw], W[o*CC + 2*kw + 1], g_wh[t], g_wl[t]);
}

__global__ void split_x_kernel(const float* __restrict__ x)
{
    size_t i4 = (size_t)blockIdx.x * 256 + threadIdx.x;   // groups of 4 words
    if (i4 >= (size_t)(NTOT/2)/4) return;
    size_t w0 = i4 * 4;
    int b  = (int)(w0 / PLANE_WORDS);
    size_t rem = w0 % PLANE_WORDS;
    int kp = (int)(rem / HWP);
    int p  = (int)(rem % HWP);
    const float* x0 = x + (size_t)b*CC*HWP + (size_t)(2*kp)*HWP + p;
    float4 v0 = *(const float4*)x0;
    float4 v1 = *(const float4*)(x0 + HWP);
    uint4 h, l;
    bfsplit2(v0.x, v1.x, h.x, l.x);
    bfsplit2(v0.y, v1.y, h.y, l.y);
    bfsplit2(v0.z, v1.z, h.z, l.z);
    bfsplit2(v0.w, v1.w, h.w, l.w);
    *(uint4*)&g_h0[w0] = h;
    *(uint4*)&g_l0[w0] = l;
}

// ---------------------------------------------------------------------------
// Tensor-core GEMM, bf16 3-split (hi*hi + lo*hi + hi*lo), m16n8k16.
//   Y[b][o][p] = sum_c W[o][c] * X[b][c][p]
// A in fragment order -> one LDS.128 per fragment. cp.async double-buffered.
// Block 128x128, BK=16 (8 packed words), 8 warps (2M x 4N), warp 64x32.
// ---------------------------------------------------------------------------
#define AW_BUF 1024          // 8 groups x 32 lanes x 4 words
#define LDBW 136
#define BW_BUF (8*LDBW)      // 1088 words

template<int EPI, int STATS>
__global__ __launch_bounds__(256, 2) void gemm_bf3(
    const uint32_t* __restrict__ Ah_g, const uint32_t* __restrict__ Al_g,
    const uint32_t* __restrict__ Bh_g, const uint32_t* __restrict__ Bl_g,
    float* __restrict__ Y, const float* __restrict__ bias,
    float* __restrict__ ps, float* __restrict__ ps2)
{
    __shared__ __align__(16) uint32_t sAh[2*AW_BUF], sAl[2*AW_BUF];
    __shared__ __align__(16) uint32_t sBh[2*BW_BUF], sBl[2*BW_BUF];
    __shared__ float sred[32], sred2[32];

    const int b   = blockIdx.z;
    const int om0 = blockIdx.y * 128;
    const int pn0 = blockIdx.x * 128;
    const int tid = threadIdx.x;
    const int lane = tid & 31;
    const int warp = tid >> 5;
    const int wm = (warp >> 2) * 64;
    const int wn = (warp & 3) * 32;
    const int r  = lane >> 2;
    const int q  = lane & 3;
    const int agbase = (warp >> 2) * 4;   // A rowgroup base for this warp

    const uint32_t* Bhb = Bh_g + (size_t)b * PLANE_WORDS;
    const uint32_t* Blb = Bl_g + (size_t)b * PLANE_WORDS;
    float* Yb = Y + (size_t)b * CC * HWP;

    const uint32_t ah_s = smem_u32(sAh), al_s = smem_u32(sAl);
    const uint32_t bh_s = smem_u32(sBh), bl_s = smem_u32(sBl);

    const int bkp = tid >> 5, bn4 = (tid & 31) * 4;

#define ISSUE_TILE(S, BUF) do { \
        int kt = (S); \
        size_t asrc = ((size_t)(kt*16 + (om0 >> 4) + (tid >> 5))*32 + (tid & 31))*4; \
        uint32_t adst = (uint32_t)((BUF)*AW_BUF + tid*4) * 4; \
        cp16(ah_s + adst, Ah_g + asrc); \
        cp16(al_s + adst, Al_g + asrc); \
        size_t bsrc = (size_t)(kt*8 + bkp) * HWP + pn0 + bn4; \
        uint32_t bdst = (uint32_t)((BUF)*BW_BUF + bkp*LDBW + bn4) * 4; \
        cp16(bh_s + bdst, Bhb + bsrc); \
        cp16(bl_s + bdst, Blb + bsrc); \
        asm volatile("cp.async.commit_group;"); \
    } while (0)

    float acc[4][4][4];
#pragma unroll
    for (int mi = 0; mi < 4; mi++)
#pragma unroll
        for (int ni = 0; ni < 4; ni++)
#pragma unroll
            for (int k = 0; k < 4; k++) acc[mi][ni][k] = 0.f;

    ISSUE_TILE(0, 0);

    for (int s = 0; s < 16; s++) {
        const int buf = s & 1;
        if (s < 15) {
            ISSUE_TILE(s + 1, buf ^ 1);
            asm volatile("cp.async.wait_group 1;");
        } else {
            asm volatile("cp.async.wait_group 0;");
        }
        __syncthreads();

        const uint32_t* Abh = sAh + buf*AW_BUF;
        const uint32_t* Abl = sAl + buf*AW_BUF;
        const uint32_t* Bbh = sBh + buf*BW_BUF;
        const uint32_t* Bbl = sBl + buf*BW_BUF;

        uint32_t ah[4][4], al[4][4];
#pragma unroll
        for (int mi = 0; mi < 4; mi++) {
            uint4 hv = *(const uint4*)&Abh[((agbase + mi)*32 + lane)*4];
            uint4 lv = *(const uint4*)&Abl[((agbase + mi)*32 + lane)*4];
            ah[mi][0]=hv.x; ah[mi][1]=hv.y; ah[mi][2]=hv.z; ah[mi][3]=hv.w;
            al[mi][0]=lv.x; al[mi][1]=lv.y; al[mi][2]=lv.z; al[mi][3]=lv.w;
        }
#pragma unroll
        for (int ni = 0; ni < 4; ni++) {
            int n0 = wn + ni*8 + r;
            uint32_t bh0 = Bbh[q*LDBW + n0], bh1 = Bbh[(q+4)*LDBW + n0];
            uint32_t bl0 = Bbl[q*LDBW + n0], bl1 = Bbl[(q+4)*LDBW + n0];
#pragma unroll
            for (int mi = 0; mi < 4; mi++) {
                mma_bf16(acc[mi][ni], ah[mi], bh0, bh1);   // hi*hi
                mma_bf16(acc[mi][ni], al[mi], bh0, bh1);   // lo*hi
                mma_bf16(acc[mi][ni], ah[mi], bl0, bl1);   // hi*lo
            }
        }
        __syncthreads();
    }

    // Epilogue. c0:(r, 2q) c1:(r, 2q+1) c2:(r+8, 2q) c3:(r+8, 2q+1)
#pragma unroll
    for (int mi = 0; mi < 4; mi++) {
        int o0 = om0 + wm + mi*16 + r;
        float bo0 = 0.f, bo1 = 0.f;
        if (EPI == 1) { bo0 = bias[o0]; bo1 = bias[o0 + 8]; }
#pragma unroll
        for (int ni = 0; ni < 4; ni++) {
            int p = pn0 + wn + ni*8 + 2*q;
            float2 v0, v1;
            v0.x = acc[mi][ni][0]; v0.y = acc[mi][ni][1];
            v1.x = acc[mi][ni][2]; v1.y = acc[mi][ni][3];
            if (EPI == 1) {
                v0.x = sigf(v0.x + bo0); v0.y = sigf(v0.y + bo0);
                v1.x = sigf(v1.x + bo1); v1.y = sigf(v1.y + bo1);
            }
            *(float2*)&Yb[(size_t)o0 * HWP + p]     = v0;
            *(float2*)&Yb[(size_t)(o0+8) * HWP + p] = v1;
        }
    }

    if (STATS) {
#pragma unroll
        for (int mi = 0; mi < 4; mi++) {
            float s = 0.f, s2 = 0.f;
#pragma unroll
            for (int ni = 0; ni < 4; ni++)
#pragma unroll
                for (int k = 0; k < 4; k++) {
                    float v = acc[mi][ni][k];
                    s += v; s2 += v*v;
                }
#pragma unroll
            for (int m = 16; m > 0; m >>= 1) {
                s  += __shfl_xor_sync(0xffffffffu, s,  m);
                s2 += __shfl_xor_sync(0xffffffffu, s2, m);
            }
            if (lane == 0) { sred[warp*4 + mi] = s; sred2[warp*4 + mi] = s2; }
        }
        __syncthreads();
        if (tid < 8) {
            int wmIdx = tid >> 2, mi = tid & 3;
            float s = 0.f, s2 = 0.f;
#pragma unroll
            for (int nIdx = 0; nIdx < 4; nIdx++) {
                int w = wmIdx*4 + nIdx;
                s += sred[w*4 + mi]; s2 += sred2[w*4 + mi];
            }
            int gsub = wmIdx*4 + mi;
            int idx = ((b*2 + blockIdx.y)*8 + gsub)*NBX + blockIdx.x;
            ps[idx] = s; ps2[idx] = s2;
        }
    }
#undef ISSUE_TILE
}

// ---------------------------------------------------------------------------
// Finalize GN stats: one block (warp) per (b,group), shfl reduce over 72.
// ---------------------------------------------------------------------------
__global__ void finalize_stats(const float* __restrict__ ps, const float* __restrict__ ps2)
{
    int bg = blockIdx.x;
    int lane = threadIdx.x;
    int base = bg * NBX;
    float s = 0.f, s2 = 0.f;
    for (int i = lane; i < NBX; i += 32) { s += ps[base+i]; s2 += ps2[base+i]; }
#pragma unroll
    for (int m = 16; m > 0; m >>= 1) {
        s  += __shfl_xor_sync(0xffffffffu, s,  m);
        s2 += __shfl_xor_sync(0xffffffffu, s2, m);
    }
    if (lane == 0) {
        float mean = s / (float)GROUPN;
        float var  = s2 / (float)GROUPN - mean*mean;
        g_mean[bg] = mean;
        g_rstd[bg] = rsqrtf(var + 1e-5f);
    }
}

// ---------------------------------------------------------------------------
// GroupNorm + SiLU; PACK=1 also emits packed bf16 hi/lo for the next GEMM.
// ---------------------------------------------------------------------------
template<int PACK>
__global__ __launch_bounds__(256) void gn_silu_k(
    const float* __restrict__ in, float* __restrict__ outf,
    const float* __restrict__ gw, const float* __restrict__ gb,
    uint32_t* __restrict__ oh, uint32_t* __restrict__ ol)
{
    size_t i4 = (size_t)blockIdx.x * 256 + threadIdx.x;
    if (i4 >= (size_t)(NTOT/2)/4) return;
    size_t w0 = i4 * 4;
    int b  = (int)(w0 / PLANE_WORDS);
    size_t rem = w0 % PLANE_WORDS;
    int kp = (int)(rem / HWP);
    int p  = (int)(rem % HWP);
    int c0 = 2*kp;
    int bg = b * GG + c0 / CPG;
    float m = g_mean[bg], rs = g_rstd[bg];
    float sw0 = gw[c0] * rs,   sb0 = gb[c0]   - m * sw0;
    float sw1 = gw[c0+1] * rs, sb1 = gb[c0+1] - m * sw1;

    size_t fidx = (size_t)b*CC*HWP + (size_t)c0*HWP + p;
    float4 v0 = *(const float4*)&in[fidx];
    float4 v1 = *(const float4*)&in[fidx + HWP];
    float y;
    y = fmaf(v0.x, sw0, sb0); v0.x = y * sigf(y);
    y = fmaf(v0.y, sw0, sb0); v0.y = y * sigf(y);
    y = fmaf(v0.z, sw0, sb0); v0.z = y * sigf(y);
    y = fmaf(v0.w, sw0, sb0); v0.w = y * sigf(y);
    y = fmaf(v1.x, sw1, sb1); v1.x = y * sigf(y);
    y = fmaf(v1.y, sw1, sb1); v1.y = y * sigf(y);
    y = fmaf(v1.z, sw1, sb1); v1.z = y * sigf(y);
    y = fmaf(v1.w, sw1, sb1); v1.w = y * sigf(y);
    *(float4*)&outf[fidx]       = v0;
    *(float4*)&outf[fidx + HWP] = v1;

    if (PACK) {
        uint4 h, l;
        bfsplit2(v0.x, v1.x, h.x, l.x);
        bfsplit2(v0.y, v1.y, h.y, l.y);
        bfsplit2(v0.z, v1.z, h.z, l.z);
        bfsplit2(v0.w, v1.w, h.w, l.w);
        *(uint4*)&oh[w0] = h;
        *(uint4*)&ol[w0] = l;
    }
}

// ---------------------------------------------------------------------------
// Fused plane kernel: 4 scans + 0.25*sum*gate + depthwise 3x3.
// Output: packed bf16 hi/lo (uint16 interleaved stores into pair layout).
// ---------------------------------------------------------------------------
#define PITCH 97
#define PLANE (HH*PITCH)
#define PLANE_SMEM (2*PLANE*4)

__global__ __launch_bounds__(256) void plane_kernel(
    const float* __restrict__ xp, const float* __restrict__ gate,
    const float* __restrict__ dww,
    uint32_t* __restrict__ dwh, uint32_t* __restrict__ dwl,
    const float* __restrict__ a_p, const float* __restrict__ b_p,
    const float* __restrict__ c_p, const float* __restrict__ d_p)
{
    extern __shared__ float sm[];
    float* xs  = sm;
    float* acc = sm + PLANE;

    const int bc  = blockIdx.x;
    const int b   = bc / CC;
    const int c   = bc % CC;
    const int tid = threadIdx.x;
    const float* xpl = xp   + (size_t)bc * HWP;
    const float* gpl = gate + (size_t)bc * HWP;

    for (int i4 = tid; i4 < HWP/4; i4 += 256) {
        float4 v = *(const float4*)&xpl[i4*4];
        int row = i4 / (WW/4), col = (i4 % (WW/4)) * 4;
        float* d = &xs[row*PITCH + col];
        d[0]=v.x; d[1]=v.y; d[2]=v.z; d[3]=v.w;
    }
    __syncthreads();

    if (tid < HH) {
        float a0 = sigf(a_p[c]),      b0 = b_p[c],      c0 = c_p[c],      d0 = d_p[c];
        float a1 = sigf(a_p[CC + c]), b1 = b_p[CC + c], c1 = c_p[CC + c], d1 = d_p[CC + c];
        float* xr = &xs[tid*PITCH];
        float* ar = &acc[tid*PITCH];
        float h = 0.f;
#pragma unroll 4
        for (int w = 0; w < WW; w++) {
            float x = xr[w];
            h = fmaf(a0, h, b0 * x);
            ar[w] = fmaf(c0, h, d0 * x);
        }
        h = 0.f;
#pragma unroll 4
        for (int w = WW-1; w >= 0; w--) {
            float x = xr[w];
            h = fmaf(a1, h, b1 * x);
            ar[w] += fmaf(c1, h, d1 * x);
        }
    }
    __syncthreads();

    if (tid < WW) {
        float a2 = sigf(a_p[2*CC + c]), b2 = b_p[2*CC + c], c2 = c_p[2*CC + c], d2 = d_p[2*CC + c];
        float a3 = sigf(a_p[3*CC + c]), b3 = b_p[3*CC + c], c3 = c_p[3*CC + c], d3 = d_p[3*CC + c];
        float h = 0.f;
#pragma unroll 4
        for (int r = 0; r < HH; r++) {
            float x = xs[r*PITCH + tid];
            h = fmaf(a2, h, b2 * x);
            acc[r*PITCH + tid] += fmaf(c2, h, d2 * x);
        }
        h = 0.f;
#pragma unroll 4
        for (int r = HH-1; r >= 0; r--) {
            float x = xs[r*PITCH + tid];
            h = fmaf(a3, h, b3 * x);
            acc[r*PITCH + tid] += fmaf(c3, h, d3 * x);
        }
    }
    __syncthreads();

    for (int i4 = tid; i4 < HWP/4; i4 += 256) {
        float4 g = *(const float4*)&gpl[i4*4];
        int row = i4 / (WW/4), col = (i4 % (WW/4)) * 4;
        float* d = &acc[row*PITCH + col];
        d[0] = 0.25f * d[0] * g.x;
        d[1] = 0.25f * d[1] * g.y;
        d[2] = 0.25f * d[2] * g.z;
        d[3] = 0.25f * d[3] * g.w;
    }
    __syncthreads();

    // Depthwise 3x3 from smem -> packed bf16 hi/lo gmem (uint16 interleave)
    const float* pk = dww + c * 9;
    float k0 = pk[0], k1 = pk[1], k2 = pk[2];
    float k3 = pk[3], k4 = pk[4], k5 = pk[5];
    float k6 = pk[6], k7 = pk[7], k8 = pk[8];
    uint16_t* oh = (uint16_t*)dwh;
    uint16_t* ol = (uint16_t*)dwl;
    size_t base16 = ((size_t)b*PLANE_WORDS + (size_t)(c >> 1)*HWP)*2 + (c & 1);
    for (int idx = tid; idx < HWP; idx += 256) {
        int row = idx / WW, col = idx % WW;
        float s = 0.f;
        if (row > 0) {
            const float* rr = &acc[(row-1)*PITCH];
            if (col > 0)    s = fmaf(rr[col-1], k0, s);
                            s = fmaf(rr[col],   k1, s);
            if (col < WW-1) s = fmaf(rr[col+1], k2, s);
        }
        {
            const float* rr = &acc[row*PITCH];
            if (col > 0)    s = fmaf(rr[col-1], k3, s);
                            s = fmaf(rr[col],   k4, s);
            if (col < WW-1) s = fmaf(rr[col+1], k5, s);
        }
        if (row < HH-1) {
            const float* rr = &acc[(row+1)*PITCH];
            if (col > 0)    s = fmaf(rr[col-1], k6, s);
                            s = fmaf(rr[col],   k7, s);
            if (col < WW-1) s = fmaf(rr[col+1], k8, s);
        }
        __nv_bfloat16 hb = __float2bfloat16_rn(s);
        float rsd = s - __bfloat162float(hb);
        oh[base16 + 2*(size_t)idx] = __bfloat16_as_ushort(hb);
        ol[base16 + 2*(size_t)idx] = __bfloat16_as_ushort(__float2bfloat16_rn(rsd));
    }
}

// ---------------------------------------------------------------------------
extern "C" void kernel_launch(void* const* d_in, const int* in_sizes, int n_in,
                              void* d_out, int out_size)
{
    const float* x      = (const float*)d_in[0];
    const float* in_w   = (const float*)d_in[1];
    const float* gn1_w  = (const float*)d_in[2];
    const float* gn1_b  = (const float*)d_in[3];
    const float* a_p    = (const float*)d_in[4];
    const float* b_p    = (const float*)d_in[5];
    const float* c_p    = (const float*)d_in[6];
    const float* d_p    = (const float*)d_in[7];
    const float* gate_w = (const float*)d_in[8];
    const float* gate_b = (const float*)d_in[9];
    const float* dw_w   = (const float*)d_in[10];
    const float* pw_w   = (const float*)d_in[11];
    const float* gn2_w  = (const float*)d_in[12];
    const float* gn2_b  = (const float*)d_in[13];
    float* out = (float*)d_out;

    float *buf0, *buf1, *buf2, *ps, *ps2;
    uint32_t *h0, *l0, *h1, *l1, *wh, *wl;
    cudaGetSymbolAddress((void**)&buf0, g_buf0);
    cudaGetSymbolAddress((void**)&buf1, g_buf1);
    cudaGetSymbolAddress((void**)&buf2, g_buf2);
    cudaGetSymbolAddress((void**)&ps,  g_ps);
    cudaGetSymbolAddress((void**)&ps2, g_ps2);
    cudaGetSymbolAddress((void**)&h0, g_h0);
    cudaGetSymbolAddress((void**)&l0, g_l0);
    cudaGetSymbolAddress((void**)&h1, g_h1);
    cudaGetSymbolAddress((void**)&l1, g_l1);
    cudaGetSymbolAddress((void**)&wh, g_wh);
    cudaGetSymbolAddress((void**)&wl, g_wl);

    cudaFuncSetAttribute(plane_kernel, cudaFuncAttributeMaxDynamicSharedMemorySize, PLANE_SMEM);

    dim3 ggrid(HWP/128, CC/128, BB);               // (72, 2, 16)
    int pair4_blocks = (int)(((size_t)(NTOT/2)/4 + 255) / 256);  // 18432

    // 0. pre-split weights + input
    split_w_kernel<<<(3*CC*KPC + 255)/256, 256>>>(in_w, gate_w, pw_w);
    split_x_kernel<<<pair4_blocks, 256>>>(x);
    // 1. xp_raw = in_w @ x   (+ fused GN1 partial stats)
    gemm_bf3<0,1><<<ggrid, 256>>>(wh, wl, h0, l0, buf0, nullptr, ps, ps2);
    // 2. finalize gn1 stats
    finalize_stats<<<BB*GG, 32>>>(ps, ps2);
    // 3. xp = silu(gn1(xp_raw))  fp32 + packed bf16 hi/lo
    gn_silu_k<1><<<pair4_blocks, 256>>>(buf0, buf1, gn1_w, gn1_b, h1, l1);
    // 4. gate = sigmoid(gate_w @ xp + gate_b)
    gemm_bf3<1,0><<<ggrid, 256>>>(wh + CC*KPC, wl + CC*KPC, h1, l1, buf2, gate_b, nullptr, nullptr);
    // 5. fused scans + gate + depthwise -> packed bf16 hi/lo (reuse h0/l0)
    plane_kernel<<<BB*CC, 256, PLANE_SMEM>>>(buf1, buf2, dw_w, h0, l0, a_p, b_p, c_p, d_p);
    // 6. out_raw = pw_w @ dw   (+ fused GN2 partial stats)
    gemm_bf3<0,1><<<ggrid, 256>>>(wh + 2*CC*KPC, wl + 2*CC*KPC, h0, l0, buf0, nullptr, ps, ps2);
    // 7. finalize gn2 stats
    finalize_stats<<<BB*GG, 32>>>(ps, ps2);
    // 8. out = silu(gn2(out_raw))
    gn_silu_k<0><<<pair4_blocks, 256>>>(buf0, out, gn2_w, gn2_b, nullptr, nullptr);
}